// round 9
// baseline (speedup 1.0000x reference)
#include <cuda_runtime.h>

#define RPB      64
#define NTHREADS 512

// ---- shared memory layout (float offsets) ----
// W_IF[lay][k(64)][q(32)] : 16B = (wi[2q], wf[2q], wi[2q+1], wf[2q+1])
// W_GO[lay][k(64)][q(32)] : 16B = (wg[2q], wo[2q], wg[2q+1], wo[2q+1])
#define OFF_WIF1 0
#define OFF_WGO1 8192
#define OFF_WIF2 16384
#define OFF_WGO2 24576
#define OFF_H    32768                  // h: 64 rows x pitch 68 (17 x float4)
#define HPITCH   68
#define OFF_X    (OFF_H + RPB*HPITCH)   // 64 x 19
#define OFF_WIH  (OFF_X + RPB*19)       // [2][256]
#define OFF_BSUM (OFF_WIH + 512)        // [2][256]
#define OFF_MW0  (OFF_BSUM + 512)
#define OFF_MB0  (OFF_MW0 + 128)
#define OFF_MW1  (OFF_MB0 + 64)
#define OFF_MB1  (OFF_MW1 + 4096)
#define OFF_MW2  (OFF_MB1 + 64)
#define OFF_MB2  (OFF_MW2 + 2048)
#define OFF_PW   (OFF_MB2 + 32)
#define OFF_PB   (OFF_PW + 576)
#define OFF_PACC (OFF_PB + 2)           // [64][2]
#define SMEM_FLOATS (OFF_PACC + RPB*2)
#define SMEM_BYTES  (SMEM_FLOATS * 4)   // ~186 KB < 227 KB

// MLP scratch reuses dead W region (after __syncthreads)
#define OFF_MH1  0                      // 64 rows x pitch 68
#define OFF_MH2  (RPB*HPITCH)

// ---- packed f32x2 helpers ----
__device__ __forceinline__ unsigned long long pack2(float a, float b) {
    unsigned long long r;
    asm("mov.b64 %0, {%1, %2};" : "=l"(r) : "f"(a), "f"(b));
    return r;
}
__device__ __forceinline__ void unpack2(unsigned long long v, float& a, float& b) {
    asm("mov.b64 {%0, %1}, %2;" : "=f"(a), "=f"(b) : "l"(v));
}
__device__ __forceinline__ void ffma2(unsigned long long& d, unsigned long long a, unsigned long long b) {
    asm("fma.rn.f32x2 %0, %1, %2, %0;" : "+l"(d) : "l"(a), "l"(b));
}

__device__ __forceinline__ float sigmoidf_(float x) {
    return __fdividef(1.0f, 1.0f + __expf(-x));
}
__device__ __forceinline__ float tanhf_(float x) {
    float e = __expf(-2.0f * x);
    return __fdividef(1.0f - e, 1.0f + e);
}

__global__ void __launch_bounds__(NTHREADS, 1)
lstm_fused_kernel(const float* __restrict__ gin,
                  const float* __restrict__ Wih1, const float* __restrict__ Whh1,
                  const float* __restrict__ bih1, const float* __restrict__ bhh1,
                  const float* __restrict__ Wih2, const float* __restrict__ Whh2,
                  const float* __restrict__ bih2, const float* __restrict__ bhh2,
                  const float* __restrict__ mW0,  const float* __restrict__ mb0,
                  const float* __restrict__ mW1,  const float* __restrict__ mb1,
                  const float* __restrict__ mW2,  const float* __restrict__ mb2,
                  const float* __restrict__ pW,   const float* __restrict__ pb,
                  float* __restrict__ out)
{
    extern __shared__ float sm[];
    const int tid = threadIdx.x;

    // ---------------- staging ----------------
    {
        const float* src = gin + (size_t)blockIdx.x * RPB * 18;
        for (int i = tid; i < RPB * 18; i += NTHREADS)
            sm[OFF_X + (i / 18) * 19 + (i % 18)] = src[i];

        // W regions: dst ((k*32 + q)*4 + e);  j = 2q + (e>>1), gate = gbase + (e&1)
        for (int idx = tid; idx < 32768; idx += NTHREADS) {
            int region = idx >> 13;            // 0:IF1 1:GO1 2:IF2 3:GO2
            int w = idx & 8191;
            int k = w >> 7, q = (w >> 2) & 31, e = w & 3;
            int j = 2 * q + (e >> 1);
            int gate = ((region & 1) ? 2 : 0) + (e & 1);
            const float* W = (region < 2) ? Whh1 : Whh2;
            sm[idx] = W[(gate * 64 + j) * 64 + k];
        }
        for (int i = tid; i < 256; i += NTHREADS) {
            sm[OFF_WIH + i]       = Wih1[i];  sm[OFF_BSUM + i]       = bih1[i] + bhh1[i];
            sm[OFF_WIH + 256 + i] = Wih2[i];  sm[OFF_BSUM + 256 + i] = bih2[i] + bhh2[i];
        }
        for (int i = tid; i < 128;  i += NTHREADS) sm[OFF_MW0 + i] = mW0[i];
        for (int i = tid; i < 4096; i += NTHREADS) sm[OFF_MW1 + i] = mW1[i];
        for (int i = tid; i < 2048; i += NTHREADS) sm[OFF_MW2 + i] = mW2[i];
        for (int i = tid; i < 64;   i += NTHREADS) { sm[OFF_MB0 + i] = mb0[i]; sm[OFF_MB1 + i] = mb1[i]; }
        for (int i = tid; i < 576;  i += NTHREADS) sm[OFF_PW + i] = pW[i];
        if (tid < 32) sm[OFF_MB2 + tid] = mb2[tid];
        if (tid < 2)  sm[OFF_PB + tid]  = pb[tid];
        __syncthreads();
    }

    // warp owns rows [4w, 4w+4) x all 64 units; lane owns units {2l, 2l+1}
    const int wrp  = tid >> 5;
    const int lane = tid & 31;
    const int row0 = wrp * 4;
    const int j0   = 2 * lane;          // first owned unit

    float c[4][2];                      // [row][unit e]
    float p0[4] = {0.f,0.f,0.f,0.f}, p1[4] = {0.f,0.f,0.f,0.f};

    #pragma unroll 1
    for (int lay = 0; lay < 2; ++lay) {
        const float* wih  = sm + OFF_WIH  + lay * 256;
        const float* bsum = sm + OFF_BSUM + lay * 256;
        const ulonglong2* wIF = reinterpret_cast<const ulonglong2*>(sm + (lay ? OFF_WIF2 : OFF_WIF1)) + lane;
        const ulonglong2* wGO = reinterpret_cast<const ulonglong2*>(sm + (lay ? OFF_WGO2 : OFF_WGO1)) + lane;

        // hoisted per-unit input weights + biases (constant across t)
        float wi[2], wf[2], wg[2], wo[2], bi[2], bf[2], bg[2], bo[2];
        #pragma unroll
        for (int e = 0; e < 2; ++e) {
            int j = j0 + e;
            wi[e] = wih[j];        bi[e] = bsum[j];
            wf[e] = wih[64 + j];   bf[e] = bsum[64 + j];
            wg[e] = wih[128 + j];  bg[e] = bsum[128 + j];
            wo[e] = wih[192 + j];  bo[e] = bsum[192 + j];
        }

        // ---- t = 0 ----
        #pragma unroll
        for (int i = 0; i < 4; ++i) {
            float x = sm[OFF_X + (row0 + i) * 19 + lay * 8];
            float hv[2];
            #pragma unroll
            for (int e = 0; e < 2; ++e) {
                float iv = sigmoidf_(fmaf(wi[e], x, bi[e]));
                float gv = tanhf_(   fmaf(wg[e], x, bg[e]));
                float ov = sigmoidf_(fmaf(wo[e], x, bo[e]));
                c[i][e] = iv * gv;
                hv[e] = ov * tanhf_(c[i][e]);
            }
            *reinterpret_cast<float2*>(sm + OFF_H + (row0 + i) * HPITCH + j0) = make_float2(hv[0], hv[1]);
        }
        __syncwarp();

        // ---- t = 1..7 ----
        #pragma unroll 1
        for (int t = 1; t < 8; ++t) {
            unsigned long long aIF[4][2], aGO[4][2];
            #pragma unroll
            for (int i = 0; i < 4; ++i) { aIF[i][0]=0ull; aIF[i][1]=0ull; aGO[i][0]=0ull; aGO[i][1]=0ull; }

            const float4* h40 = reinterpret_cast<const float4*>(sm + OFF_H + (row0)     * HPITCH);
            const float4* h41 = reinterpret_cast<const float4*>(sm + OFF_H + (row0 + 1) * HPITCH);
            const float4* h42 = reinterpret_cast<const float4*>(sm + OFF_H + (row0 + 2) * HPITCH);
            const float4* h43 = reinterpret_cast<const float4*>(sm + OFF_H + (row0 + 3) * HPITCH);

            #pragma unroll 2
            for (int kg = 0; kg < 16; ++kg) {
                float4 a0 = h40[kg], a1 = h41[kg], a2 = h42[kg], a3 = h43[kg];
                const float* f0 = reinterpret_cast<const float*>(&a0);
                const float* f1 = reinterpret_cast<const float*>(&a1);
                const float* f2 = reinterpret_cast<const float*>(&a2);
                const float* f3 = reinterpret_cast<const float*>(&a3);
                #pragma unroll
                for (int kk = 0; kk < 4; ++kk) {
                    int k = (kg << 2) + kk;
                    ulonglong2 vIF = wIF[k << 5];        // conflict-free: lane-contiguous
                    ulonglong2 vGO = wGO[k << 5];
                    unsigned long long h0 = pack2(f0[kk], f0[kk]);
                    unsigned long long h1 = pack2(f1[kk], f1[kk]);
                    unsigned long long h2 = pack2(f2[kk], f2[kk]);
                    unsigned long long h3 = pack2(f3[kk], f3[kk]);
                    ffma2(aIF[0][0], vIF.x, h0); ffma2(aIF[0][1], vIF.y, h0);
                    ffma2(aGO[0][0], vGO.x, h0); ffma2(aGO[0][1], vGO.y, h0);
                    ffma2(aIF[1][0], vIF.x, h1); ffma2(aIF[1][1], vIF.y, h1);
                    ffma2(aGO[1][0], vGO.x, h1); ffma2(aGO[1][1], vGO.y, h1);
                    ffma2(aIF[2][0], vIF.x, h2); ffma2(aIF[2][1], vIF.y, h2);
                    ffma2(aGO[2][0], vGO.x, h2); ffma2(aGO[2][1], vGO.y, h2);
                    ffma2(aIF[3][0], vIF.x, h3); ffma2(aIF[3][1], vIF.y, h3);
                    ffma2(aGO[3][0], vGO.x, h3); ffma2(aGO[3][1], vGO.y, h3);
                }
            }
            __syncwarp();   // all lanes done reading h[t-1]

            if (t < 7) {
                #pragma unroll
                for (int i = 0; i < 4; ++i) {
                    float x = sm[OFF_X + (row0 + i) * 19 + lay * 8 + t];
                    float hv[2];
                    #pragma unroll
                    for (int e = 0; e < 2; ++e) {
                        float aI, aF, aG, aO;
                        unpack2(aIF[i][e], aI, aF);
                        unpack2(aGO[i][e], aG, aO);
                        float iv = sigmoidf_(aI + fmaf(wi[e], x, bi[e]));
                        float fv = sigmoidf_(aF + fmaf(wf[e], x, bf[e]));
                        float gv = tanhf_(   aG + fmaf(wg[e], x, bg[e]));
                        float ov = sigmoidf_(aO + fmaf(wo[e], x, bo[e]));
                        c[i][e] = fmaf(fv, c[i][e], iv * gv);
                        hv[e] = ov * tanhf_(c[i][e]);
                    }
                    *reinterpret_cast<float2*>(sm + OFF_H + (row0 + i) * HPITCH + j0) = make_float2(hv[0], hv[1]);
                }
                __syncwarp();
            } else {
                // t == 7: fuse projection partials, no h store
                const float* pWs = sm + OFF_PW;
                const int zb = lay * 128;
                #pragma unroll
                for (int i = 0; i < 4; ++i) {
                    float x = sm[OFF_X + (row0 + i) * 19 + lay * 8 + 7];
                    #pragma unroll
                    for (int e = 0; e < 2; ++e) {
                        int j = j0 + e;
                        float aI, aF, aG, aO;
                        unpack2(aIF[i][e], aI, aF);
                        unpack2(aGO[i][e], aG, aO);
                        float iv = sigmoidf_(aI + fmaf(wi[e], x, bi[e]));
                        float fv = sigmoidf_(aF + fmaf(wf[e], x, bf[e]));
                        float gv = tanhf_(   aG + fmaf(wg[e], x, bg[e]));
                        float ov = sigmoidf_(aO + fmaf(wo[e], x, bo[e]));
                        float cv = fmaf(fv, c[i][e], iv * gv);
                        float hv = ov * tanhf_(cv);
                        p0[i] = fmaf(hv, pWs[zb + j],       fmaf(cv, pWs[zb + 64 + j],       p0[i]));
                        p1[i] = fmaf(hv, pWs[288 + zb + j], fmaf(cv, pWs[288 + zb + 64 + j], p1[i]));
                    }
                }
                __syncwarp();
            }
        }
    }

    // warp butterfly reduction of projection partials; lanes 0..7 store
    #pragma unroll
    for (int s = 16; s >= 1; s >>= 1) {
        #pragma unroll
        for (int i = 0; i < 4; ++i) {
            p0[i] += __shfl_xor_sync(0xffffffffu, p0[i], s);
            p1[i] += __shfl_xor_sync(0xffffffffu, p1[i], s);
        }
    }
    if (lane < 8) {
        int i = lane >> 1, o = lane & 1;
        sm[OFF_PACC + (row0 + i) * 2 + o] = o ? p1[i] : p0[i];
    }
    __syncthreads();   // W region dead; PACC base written

    // ---------------- MLP on feat (8 threads per row, scratch in dead W region) ----------------
    {
        const int mr = tid >> 3, mq = tid & 7;
        const float* xr = sm + OFF_X + mr * 19;
        float f0v = xr[16], f1v = xr[17];
        float* h1 = sm + OFF_MH1 + mr * HPITCH;
        float* h2 = sm + OFF_MH2 + mr * HPITCH;

        #pragma unroll
        for (int u = 0; u < 8; ++u) {
            int j = mq * 8 + u;
            float v = fmaf(sm[OFF_MW0 + j * 2], f0v,
                      fmaf(sm[OFF_MW0 + j * 2 + 1], f1v, sm[OFF_MB0 + j]));
            h1[j] = fmaxf(v, 0.f);
        }
        __syncwarp();

        #pragma unroll
        for (int u = 0; u < 8; ++u) {
            int j = mq * 8 + u;
            float acc = sm[OFF_MB1 + j];
            const float* wr = sm + OFF_MW1 + j * 64;
            #pragma unroll 8
            for (int k = 0; k < 64; ++k) acc = fmaf(h1[k], wr[k], acc);
            h2[j] = fmaxf(acc, 0.f);
        }
        __syncwarp();

        const float* pWs = sm + OFF_PW;
        float pa0 = 0.f, pa1 = 0.f;
        #pragma unroll
        for (int u2 = 0; u2 < 4; ++u2) {
            int j2 = mq * 4 + u2;
            float acc = sm[OFF_MB2 + j2];
            const float* wr = sm + OFF_MW2 + j2 * 64;
            #pragma unroll 8
            for (int k = 0; k < 64; ++k) acc = fmaf(h2[k], wr[k], acc);
            pa0 = fmaf(acc, pWs[256 + j2], pa0);
            pa1 = fmaf(acc, pWs[544 + j2], pa1);
        }
        atomicAdd(&sm[OFF_PACC + mr * 2 + 0], pa0);
        atomicAdd(&sm[OFF_PACC + mr * 2 + 1], pa1);
    }
    __syncthreads();

    if (tid < RPB * 2) {
        int rl = tid >> 1, mm = tid & 1;
        size_t row = (size_t)blockIdx.x * RPB + (size_t)rl;
        out[row * 2 + mm] = sm[OFF_PACC + rl * 2 + mm] + sm[OFF_PB + mm];
    }
}

extern "C" void kernel_launch(void* const* d_in, const int* in_sizes, int n_in,
                              void* d_out, int out_size)
{
    const float* gin  = (const float*)d_in[0];
    const float* Wih1 = (const float*)d_in[1];
    const float* Whh1 = (const float*)d_in[2];
    const float* bih1 = (const float*)d_in[3];
    const float* bhh1 = (const float*)d_in[4];
    const float* Wih2 = (const float*)d_in[5];
    const float* Whh2 = (const float*)d_in[6];
    const float* bih2 = (const float*)d_in[7];
    const float* bhh2 = (const float*)d_in[8];
    const float* mW0  = (const float*)d_in[9];
    const float* mb0  = (const float*)d_in[10];
    const float* mW1  = (const float*)d_in[11];
    const float* mb1  = (const float*)d_in[12];
    const float* mW2  = (const float*)d_in[13];
    const float* mb2  = (const float*)d_in[14];
    const float* pW   = (const float*)d_in[15];
    const float* pb   = (const float*)d_in[16];

    int rows = in_sizes[0] / 18;
    int grid = rows / RPB;

    cudaFuncSetAttribute(lstm_fused_kernel,
                         cudaFuncAttributeMaxDynamicSharedMemorySize, SMEM_BYTES);

    lstm_fused_kernel<<<grid, NTHREADS, SMEM_BYTES>>>(
        gin, Wih1, Whh1, bih1, bhh1, Wih2, Whh2, bih2, bhh2,
        mW0, mb0, mW1, mb1, mW2, mb2, pW, pb, (float*)d_out);
}

// round 10
// speedup vs baseline: 1.2057x; 1.2057x over previous
#include <cuda_runtime.h>

#define RPB      128
#define NTHREADS 512

// ---- shared memory layout (float offsets) ----
#define OFF_W    0                       // current layer Whh: [k(64)][j(64)][4 gates] = 16384
#define OFF_HA   16384                   // h ping buffer: 128 rows x pitch 68
#define HPITCH   68
#define OFF_HB   (OFF_HA + RPB*HPITCH)   // h pong buffer
#define OFF_X    (OFF_HB + RPB*HPITCH)   // inputs: 128 rows x pitch 19
#define OFF_C    (OFF_X + RPB*19)        // c state: 512 threads x pitch 17 (conflict-free)
#define CPITCH   17
#define OFF_WIH  (OFF_C + NTHREADS*CPITCH)  // [2][256]
#define OFF_BSUM (OFF_WIH + 512)            // [2][256]
#define OFF_MW0  (OFF_BSUM + 512)
#define OFF_MB0  (OFF_MW0 + 128)
#define OFF_MW1  (OFF_MB0 + 64)
#define OFF_MB1  (OFF_MW1 + 4096)
#define OFF_MW2  (OFF_MB1 + 64)
#define OFF_MB2  (OFF_MW2 + 2048)
#define OFF_PW   (OFF_MB2 + 32)
#define OFF_PB   (OFF_PW + 576)
#define OFF_PACC (OFF_PB + 2)            // per-row projection accumulators [128][2]
#define SMEM_FLOATS (OFF_PACC + RPB*2)
#define SMEM_BYTES  (SMEM_FLOATS * 4)    // ~213 KB < 227 KB

// MLP scratch reuses the (dead after LSTMs) h buffers
#define OFF_MH1  OFF_HA
#define OFF_MH2  OFF_HB

// ---- packed f32x2 helpers (Blackwell sm_103a) ----
__device__ __forceinline__ unsigned long long pack2(float a, float b) {
    unsigned long long r;
    asm("mov.b64 %0, {%1, %2};" : "=l"(r) : "f"(a), "f"(b));
    return r;
}
__device__ __forceinline__ void unpack2(unsigned long long v, float& a, float& b) {
    asm("mov.b64 {%0, %1}, %2;" : "=f"(a), "=f"(b) : "l"(v));
}
__device__ __forceinline__ void ffma2(unsigned long long& d, unsigned long long a, unsigned long long b) {
    asm("fma.rn.f32x2 %0, %1, %2, %0;" : "+l"(d) : "l"(a), "l"(b));
}

__device__ __forceinline__ float sigmoidf_(float x) {
    return __fdividef(1.0f, 1.0f + __expf(-x));
}
__device__ __forceinline__ float tanhf_(float x) {
    float e = __expf(-2.0f * x);
    return __fdividef(1.0f - e, 1.0f + e);
}

__global__ void __launch_bounds__(NTHREADS, 1)
lstm_fused_kernel(const float* __restrict__ gin,
                  const float* __restrict__ Wih1, const float* __restrict__ Whh1,
                  const float* __restrict__ bih1, const float* __restrict__ bhh1,
                  const float* __restrict__ Wih2, const float* __restrict__ Whh2,
                  const float* __restrict__ bih2, const float* __restrict__ bhh2,
                  const float* __restrict__ mW0,  const float* __restrict__ mb0,
                  const float* __restrict__ mW1,  const float* __restrict__ mb1,
                  const float* __restrict__ mW2,  const float* __restrict__ mb2,
                  const float* __restrict__ pW,   const float* __restrict__ pb,
                  float* __restrict__ out)
{
    extern __shared__ float sm[];
    const int tid = threadIdx.x;

    // ---------------- staging ----------------
    {
        const float* src = gin + (size_t)blockIdx.x * RPB * 18;
        for (int i = tid; i < RPB * 18; i += NTHREADS)
            sm[OFF_X + (i / 18) * 19 + (i % 18)] = src[i];

        // Whh1[rowi = g*64 + j][k]  ->  W[(k*64 + j)*4 + g]
        for (int i = tid; i < 16384; i += NTHREADS) {
            int k = i & 63, rowi = i >> 6;
            int g = rowi >> 6, j = rowi & 63;
            sm[OFF_W + ((k << 6) + j) * 4 + g] = Whh1[i];
        }
        for (int i = tid; i < 256; i += NTHREADS) {
            sm[OFF_WIH + i]       = Wih1[i];  sm[OFF_BSUM + i]       = bih1[i] + bhh1[i];
            sm[OFF_WIH + 256 + i] = Wih2[i];  sm[OFF_BSUM + 256 + i] = bih2[i] + bhh2[i];
        }
        for (int i = tid; i < 128;  i += NTHREADS) sm[OFF_MW0 + i] = mW0[i];
        for (int i = tid; i < 4096; i += NTHREADS) sm[OFF_MW1 + i] = mW1[i];
        for (int i = tid; i < 2048; i += NTHREADS) sm[OFF_MW2 + i] = mW2[i];
        for (int i = tid; i < 64;   i += NTHREADS) { sm[OFF_MB0 + i] = mb0[i]; sm[OFF_MB1 + i] = mb1[i]; }
        for (int i = tid; i < 576;  i += NTHREADS) sm[OFF_PW + i] = pW[i];
        for (int i = tid; i < RPB * 2; i += NTHREADS) sm[OFF_PACC + i] = 0.f;
        if (tid < 32) sm[OFF_MB2 + tid] = mb2[tid];
        if (tid < 2)  sm[OFF_PB + tid]  = pb[tid];
        __syncthreads();
    }

    // warp w (0..15) owns units [4w, 4w+4); lane l owns rows {l, l+32, l+64, l+96}
    const int wrp   = tid >> 5;
    const int lane  = tid & 31;
    const int jbase = wrp * 4;
    float* cst = sm + OFF_C + tid * CPITCH;     // 16 c values: [i*4+u]

    #pragma unroll 1
    for (int lay = 0; lay < 2; ++lay) {
        const float* wih  = sm + OFF_WIH  + lay * 256;
        const float* bsum = sm + OFF_BSUM + lay * 256;
        const ulonglong2* wp = reinterpret_cast<const ulonglong2*>(sm + OFF_W) + jbase;

        // ---- t = 0 (h == 0, c == 0): write h into buf A ----
        {
            #pragma unroll
            for (int i = 0; i < 4; ++i) {
                float x = sm[OFF_X + (lane + 32 * i) * 19 + lay * 8];
                float hv[4];
                #pragma unroll
                for (int u = 0; u < 4; ++u) {
                    int j = jbase + u;
                    float iv = sigmoidf_(fmaf(wih[j],       x, bsum[j]));
                    float gv = tanhf_(   fmaf(wih[128 + j], x, bsum[128 + j]));
                    float ov = sigmoidf_(fmaf(wih[192 + j], x, bsum[192 + j]));
                    float cv = iv * gv;
                    cst[i * 4 + u] = cv;
                    hv[u] = ov * tanhf_(cv);
                }
                *reinterpret_cast<float4*>(sm + OFF_HA + (lane + 32 * i) * HPITCH + jbase)
                    = make_float4(hv[0], hv[1], hv[2], hv[3]);
            }
            __syncthreads();
        }

        // ---- t = 1..7: read buf[(t-1)&1], write buf[t&1] ----
        #pragma unroll 1
        for (int t = 1; t < 8; ++t) {
            const int rdoff = ((t - 1) & 1) ? OFF_HB : OFF_HA;
            const int wroff = (t & 1) ? OFF_HB : OFF_HA;

            unsigned long long aIF[4][4], aGO[4][4];
            #pragma unroll
            for (int i = 0; i < 4; ++i)
                #pragma unroll
                for (int u = 0; u < 4; ++u) { aIF[i][u] = 0ull; aGO[i][u] = 0ull; }

            const float4* h4p0 = reinterpret_cast<const float4*>(sm + rdoff + (lane)      * HPITCH);
            const float4* h4p1 = reinterpret_cast<const float4*>(sm + rdoff + (lane + 32) * HPITCH);
            const float4* h4p2 = reinterpret_cast<const float4*>(sm + rdoff + (lane + 64) * HPITCH);
            const float4* h4p3 = reinterpret_cast<const float4*>(sm + rdoff + (lane + 96) * HPITCH);

            #pragma unroll 1
            for (int kg = 0; kg < 16; ++kg) {
                float4 h40 = h4p0[kg], h41 = h4p1[kg], h42 = h4p2[kg], h43 = h4p3[kg];
                const float* hf0 = reinterpret_cast<const float*>(&h40);
                const float* hf1 = reinterpret_cast<const float*>(&h41);
                const float* hf2 = reinterpret_cast<const float*>(&h42);
                const float* hf3 = reinterpret_cast<const float*>(&h43);
                #pragma unroll
                for (int kk = 0; kk < 4; ++kk) {
                    unsigned long long hk0 = pack2(hf0[kk], hf0[kk]);
                    unsigned long long hk1 = pack2(hf1[kk], hf1[kk]);
                    unsigned long long hk2 = pack2(hf2[kk], hf2[kk]);
                    unsigned long long hk3 = pack2(hf3[kk], hf3[kk]);
                    const ulonglong2* wk = wp + (((kg << 2) + kk) << 6);
                    #pragma unroll
                    for (int u = 0; u < 4; ++u) {
                        ulonglong2 wv = wk[u];                  // broadcast across warp
                        ffma2(aIF[0][u], wv.x, hk0); ffma2(aGO[0][u], wv.y, hk0);
                        ffma2(aIF[1][u], wv.x, hk1); ffma2(aGO[1][u], wv.y, hk1);
                        ffma2(aIF[2][u], wv.x, hk2); ffma2(aGO[2][u], wv.y, hk2);
                        ffma2(aIF[3][u], wv.x, hk3); ffma2(aGO[3][u], wv.y, hk3);
                    }
                }
            }

            // epilogue: i-outer, one float4 h store per row
            if (t < 7) {
                #pragma unroll
                for (int i = 0; i < 4; ++i) {
                    float x = sm[OFF_X + (lane + 32 * i) * 19 + lay * 8 + t];
                    float hv[4];
                    #pragma unroll
                    for (int u = 0; u < 4; ++u) {
                        int j = jbase + u;
                        float aI, aF, aG, aO;
                        unpack2(aIF[i][u], aI, aF);
                        unpack2(aGO[i][u], aG, aO);
                        float iv = sigmoidf_(aI + fmaf(wih[j],       x, bsum[j]));
                        float fv = sigmoidf_(aF + fmaf(wih[64 + j],  x, bsum[64 + j]));
                        float gv = tanhf_(   aG + fmaf(wih[128 + j], x, bsum[128 + j]));
                        float ov = sigmoidf_(aO + fmaf(wih[192 + j], x, bsum[192 + j]));
                        float cv = fmaf(fv, cst[i * 4 + u], iv * gv);
                        cst[i * 4 + u] = cv;
                        hv[u] = ov * tanhf_(cv);
                    }
                    *reinterpret_cast<float4*>(sm + wroff + (lane + 32 * i) * HPITCH + jbase)
                        = make_float4(hv[0], hv[1], hv[2], hv[3]);
                }
                __syncthreads();
            } else {
                // t == 7: no h store; fuse projection partials
                const float* pWs = sm + OFF_PW;
                const int zb = lay * 128;
                #pragma unroll
                for (int i = 0; i < 4; ++i) {
                    float x = sm[OFF_X + (lane + 32 * i) * 19 + lay * 8 + 7];
                    float p0 = 0.f, p1 = 0.f;
                    #pragma unroll
                    for (int u = 0; u < 4; ++u) {
                        int j = jbase + u;
                        float aI, aF, aG, aO;
                        unpack2(aIF[i][u], aI, aF);
                        unpack2(aGO[i][u], aG, aO);
                        float iv = sigmoidf_(aI + fmaf(wih[j],       x, bsum[j]));
                        float fv = sigmoidf_(aF + fmaf(wih[64 + j],  x, bsum[64 + j]));
                        float gv = tanhf_(   aG + fmaf(wih[128 + j], x, bsum[128 + j]));
                        float ov = sigmoidf_(aO + fmaf(wih[192 + j], x, bsum[192 + j]));
                        float cv = fmaf(fv, cst[i * 4 + u], iv * gv);
                        float hv = ov * tanhf_(cv);
                        p0 = fmaf(hv, pWs[zb + j],       fmaf(cv, pWs[zb + 64 + j],       p0));
                        p1 = fmaf(hv, pWs[288 + zb + j], fmaf(cv, pWs[288 + zb + 64 + j], p1));
                    }
                    atomicAdd(&sm[OFF_PACC + (lane + 32 * i) * 2 + 0], p0);
                    atomicAdd(&sm[OFF_PACC + (lane + 32 * i) * 2 + 1], p1);
                }
                __syncthreads();
            }
        }

        // ---- stage layer-2 weights (after layer 0 only) ----
        if (lay == 0) {
            for (int i = tid; i < 16384; i += NTHREADS) {
                int k = i & 63, rowi = i >> 6;
                int g = rowi >> 6, j = rowi & 63;
                sm[OFF_W + ((k << 6) + j) * 4 + g] = Whh2[i];
            }
            __syncthreads();
        }
    }

    // ---------------- MLP on feat (4 threads per row, scratch in dead h buffers) ----------------
    {
        const int mr = tid >> 2, mq = tid & 3;
        const float* xr = sm + OFF_X + mr * 19;
        float f0 = xr[16], f1 = xr[17];
        float* h1 = sm + OFF_MH1 + mr * HPITCH;
        float* h2 = sm + OFF_MH2 + mr * HPITCH;

        #pragma unroll
        for (int u = 0; u < 16; ++u) {
            int j = mq * 16 + u;
            float v = fmaf(sm[OFF_MW0 + j * 2], f0,
                      fmaf(sm[OFF_MW0 + j * 2 + 1], f1, sm[OFF_MB0 + j]));
            h1[j] = fmaxf(v, 0.f);
        }
        __syncwarp();

        #pragma unroll
        for (int u = 0; u < 16; ++u) {
            int j = mq * 16 + u;
            float acc = sm[OFF_MB1 + j];
            const float* wr = sm + OFF_MW1 + j * 64;
            #pragma unroll 8
            for (int k = 0; k < 64; ++k) acc = fmaf(h1[k], wr[k], acc);
            h2[j] = fmaxf(acc, 0.f);
        }
        __syncwarp();

        const float* pWs = sm + OFF_PW;
        float pa0 = 0.f, pa1 = 0.f;
        #pragma unroll
        for (int u2 = 0; u2 < 8; ++u2) {
            int j2 = mq * 8 + u2;
            float acc = sm[OFF_MB2 + j2];
            const float* wr = sm + OFF_MW2 + j2 * 64;
            #pragma unroll 8
            for (int k = 0; k < 64; ++k) acc = fmaf(h2[k], wr[k], acc);
            pa0 = fmaf(acc, pWs[256 + j2], pa0);
            pa1 = fmaf(acc, pWs[544 + j2], pa1);
        }
        atomicAdd(&sm[OFF_PACC + mr * 2 + 0], pa0);
        atomicAdd(&sm[OFF_PACC + mr * 2 + 1], pa1);
    }
    __syncthreads();

    if (tid < RPB * 2) {
        int rl = tid >> 1, mm = tid & 1;
        size_t row = (size_t)blockIdx.x * RPB + (size_t)rl;
        out[row * 2 + mm] = sm[OFF_PACC + rl * 2 + mm] + sm[OFF_PB + mm];
    }
}

extern "C" void kernel_launch(void* const* d_in, const int* in_sizes, int n_in,
                              void* d_out, int out_size)
{
    const float* gin  = (const float*)d_in[0];
    const float* Wih1 = (const float*)d_in[1];
    const float* Whh1 = (const float*)d_in[2];
    const float* bih1 = (const float*)d_in[3];
    const float* bhh1 = (const float*)d_in[4];
    const float* Wih2 = (const float*)d_in[5];
    const float* Whh2 = (const float*)d_in[6];
    const float* bih2 = (const float*)d_in[7];
    const float* bhh2 = (const float*)d_in[8];
    const float* mW0  = (const float*)d_in[9];
    const float* mb0  = (const float*)d_in[10];
    const float* mW1  = (const float*)d_in[11];
    const float* mb1  = (const float*)d_in[12];
    const float* mW2  = (const float*)d_in[13];
    const float* mb2  = (const float*)d_in[14];
    const float* pW   = (const float*)d_in[15];
    const float* pb   = (const float*)d_in[16];

    int rows = in_sizes[0] / 18;
    int grid = rows / RPB;

    cudaFuncSetAttribute(lstm_fused_kernel,
                         cudaFuncAttributeMaxDynamicSharedMemorySize, SMEM_BYTES);

    lstm_fused_kernel<<<grid, NTHREADS, SMEM_BYTES>>>(
        gin, Wih1, Whh1, bih1, bhh1, Wih2, Whh2, bih2, bhh2,
        mW0, mb0, mW1, mb1, mW2, mb2, pW, pb, (float*)d_out);
}

// round 11
// speedup vs baseline: 1.3301x; 1.1031x over previous
#include <cuda_runtime.h>

#define RPB      128
#define NTHREADS 256

// ---- shared memory layout (float offsets) ----
#define OFF_W    0                       // current layer Whh: [k(64)][j(64)][4 gates] = 16384
#define OFF_HA   16384                   // h ping: 128 rows x pitch 68
#define HPITCH   68
#define OFF_HB   (OFF_HA + RPB*HPITCH)   // h pong
#define OFF_X    (OFF_HB + RPB*HPITCH)   // 128 x 19
#define OFF_C    (OFF_X + RPB*19)        // c: 256 threads x pitch 33
#define CPITCH   33
#define OFF_WIH  (OFF_C + NTHREADS*CPITCH)
#define OFF_BSUM (OFF_WIH + 512)
#define OFF_MW0  (OFF_BSUM + 512)
#define OFF_MB0  (OFF_MW0 + 128)
#define OFF_MW1  (OFF_MB0 + 64)
#define OFF_MB1  (OFF_MW1 + 4096)
#define OFF_MW2  (OFF_MB1 + 64)
#define OFF_MB2  (OFF_MW2 + 2048)
#define OFF_PW   (OFF_MB2 + 32)
#define OFF_PB   (OFF_PW + 576)
#define OFF_PACC (OFF_PB + 2)            // [128][2]
#define SMEM_FLOATS (OFF_PACC + RPB*2)
#define SMEM_BYTES  (SMEM_FLOATS * 4)    // ~212 KB < 227 KB

// MLP scratch reuses dead h buffers
#define OFF_MH1  OFF_HA
#define OFF_MH2  OFF_HB

// ---- packed f32x2 helpers ----
__device__ __forceinline__ unsigned long long pack2(float a, float b) {
    unsigned long long r;
    asm("mov.b64 %0, {%1, %2};" : "=l"(r) : "f"(a), "f"(b));
    return r;
}
__device__ __forceinline__ void unpack2(unsigned long long v, float& a, float& b) {
    asm("mov.b64 {%0, %1}, %2;" : "=f"(a), "=f"(b) : "l"(v));
}
__device__ __forceinline__ void ffma2(unsigned long long& d, unsigned long long a, unsigned long long b) {
    asm("fma.rn.f32x2 %0, %1, %2, %0;" : "+l"(d) : "l"(a), "l"(b));
}
__device__ __forceinline__ void grp_bar(int id) {
    asm volatile("bar.sync %0, %1;" :: "r"(id), "r"(128) : "memory");
}

__device__ __forceinline__ float sigmoidf_(float x) {
    return __fdividef(1.0f, 1.0f + __expf(-x));
}
__device__ __forceinline__ float tanhf_(float x) {
    float e = __expf(-2.0f * x);
    return __fdividef(1.0f - e, 1.0f + e);
}

__global__ void __launch_bounds__(NTHREADS, 1)
lstm_fused_kernel(const float* __restrict__ gin,
                  const float* __restrict__ Wih1, const float* __restrict__ Whh1,
                  const float* __restrict__ bih1, const float* __restrict__ bhh1,
                  const float* __restrict__ Wih2, const float* __restrict__ Whh2,
                  const float* __restrict__ bih2, const float* __restrict__ bhh2,
                  const float* __restrict__ mW0,  const float* __restrict__ mb0,
                  const float* __restrict__ mW1,  const float* __restrict__ mb1,
                  const float* __restrict__ mW2,  const float* __restrict__ mb2,
                  const float* __restrict__ pW,   const float* __restrict__ pb,
                  float* __restrict__ out)
{
    extern __shared__ float sm[];
    const int tid = threadIdx.x;

    // ---------------- staging ----------------
    {
        const float* src = gin + (size_t)blockIdx.x * RPB * 18;
        for (int i = tid; i < RPB * 18; i += NTHREADS)
            sm[OFF_X + (i / 18) * 19 + (i % 18)] = src[i];

        // Whh1[(g*64 + j)*64 + k]  ->  W[((k*64 + j)*4) + g]
        for (int i = tid; i < 16384; i += NTHREADS) {
            int k = i & 63, rowi = i >> 6;
            int g = rowi >> 6, j = rowi & 63;
            sm[OFF_W + ((k << 6) + j) * 4 + g] = Whh1[i];
        }
        for (int i = tid; i < 256; i += NTHREADS) {
            sm[OFF_WIH + i]       = Wih1[i];  sm[OFF_BSUM + i]       = bih1[i] + bhh1[i];
            sm[OFF_WIH + 256 + i] = Wih2[i];  sm[OFF_BSUM + 256 + i] = bih2[i] + bhh2[i];
        }
        for (int i = tid; i < 128;  i += NTHREADS) sm[OFF_MW0 + i] = mW0[i];
        for (int i = tid; i < 4096; i += NTHREADS) sm[OFF_MW1 + i] = mW1[i];
        for (int i = tid; i < 2048; i += NTHREADS) sm[OFF_MW2 + i] = mW2[i];
        for (int i = tid; i < 64;   i += NTHREADS) { sm[OFF_MB0 + i] = mb0[i]; sm[OFF_MB1 + i] = mb1[i]; }
        for (int i = tid; i < 576;  i += NTHREADS) sm[OFF_PW + i] = pW[i];
        for (int i = tid; i < RPB * 2; i += NTHREADS) sm[OFF_PACC + i] = 0.f;
        if (tid < 32) sm[OFF_MB2 + tid] = mb2[tid];
        if (tid < 2)  sm[OFF_PB + tid]  = pb[tid];
        __syncthreads();
    }

    // group g = wrp>>2 owns rows [64g, 64g+64); within group, warp w' owns units [16w', 16w'+16)
    // lane owns rows {64g+lane, 64g+lane+32}
    const int wrp  = tid >> 5;
    const int lane = tid & 31;
    const int grp  = wrp >> 2;
    const int wq   = wrp & 3;
    const int u0   = wq * 16;
    const int r0   = grp * 64 + lane;         // first owned row
    const int barid = grp + 1;                // named barriers 1, 2
    float* cst = sm + OFF_C + tid * CPITCH;   // 32 c values: [i*16+u]

    #pragma unroll 1
    for (int lay = 0; lay < 2; ++lay) {
        const float* wih  = sm + OFF_WIH  + lay * 256;
        const float* bsum = sm + OFF_BSUM + lay * 256;
        const ulonglong2* wp = reinterpret_cast<const ulonglong2*>(sm + OFF_W) + u0;

        // ---- t = 0 (h == 0, c == 0): write h into buf A ----
        {
            #pragma unroll
            for (int i = 0; i < 2; ++i) {
                int r = r0 + 32 * i;
                float x = sm[OFF_X + r * 19 + lay * 8];
                #pragma unroll
                for (int uq = 0; uq < 4; ++uq) {
                    float hv[4];
                    #pragma unroll
                    for (int e = 0; e < 4; ++e) {
                        int u = uq * 4 + e, j = u0 + u;
                        float iv = sigmoidf_(fmaf(wih[j],       x, bsum[j]));
                        float gv = tanhf_(   fmaf(wih[128 + j], x, bsum[128 + j]));
                        float ov = sigmoidf_(fmaf(wih[192 + j], x, bsum[192 + j]));
                        float cv = iv * gv;
                        cst[i * 16 + u] = cv;
                        hv[e] = ov * tanhf_(cv);
                    }
                    *reinterpret_cast<float4*>(sm + OFF_HA + r * HPITCH + u0 + uq * 4)
                        = make_float4(hv[0], hv[1], hv[2], hv[3]);
                }
            }
            grp_bar(barid);
        }

        // ---- t = 1..7 ----
        #pragma unroll 1
        for (int t = 1; t < 8; ++t) {
            const int rdoff = ((t - 1) & 1) ? OFF_HB : OFF_HA;
            const int wroff = (t & 1) ? OFF_HB : OFF_HA;

            unsigned long long aIF[2][16], aGO[2][16];
            #pragma unroll
            for (int i = 0; i < 2; ++i)
                #pragma unroll
                for (int u = 0; u < 16; ++u) { aIF[i][u] = 0ull; aGO[i][u] = 0ull; }

            const float4* h4a = reinterpret_cast<const float4*>(sm + rdoff + (r0)      * HPITCH);
            const float4* h4b = reinterpret_cast<const float4*>(sm + rdoff + (r0 + 32) * HPITCH);

            #pragma unroll 2
            for (int kg = 0; kg < 16; ++kg) {
                float4 ha = h4a[kg], hb = h4b[kg];
                const float* fa = reinterpret_cast<const float*>(&ha);
                const float* fb = reinterpret_cast<const float*>(&hb);
                #pragma unroll
                for (int kk = 0; kk < 4; ++kk) {
                    unsigned long long hk0 = pack2(fa[kk], fa[kk]);
                    unsigned long long hk1 = pack2(fb[kk], fb[kk]);
                    const ulonglong2* wk = wp + (((kg << 2) + kk) << 6);
                    #pragma unroll
                    for (int u = 0; u < 16; ++u) {
                        ulonglong2 wv = wk[u];                 // broadcast across warp
                        ffma2(aIF[0][u], wv.x, hk0); ffma2(aGO[0][u], wv.y, hk0);
                        ffma2(aIF[1][u], wv.x, hk1); ffma2(aGO[1][u], wv.y, hk1);
                    }
                }
            }

            if (t < 7) {
                #pragma unroll
                for (int i = 0; i < 2; ++i) {
                    int r = r0 + 32 * i;
                    float x = sm[OFF_X + r * 19 + lay * 8 + t];
                    #pragma unroll
                    for (int uq = 0; uq < 4; ++uq) {
                        float hv[4];
                        #pragma unroll
                        for (int e = 0; e < 4; ++e) {
                            int u = uq * 4 + e, j = u0 + u;
                            float aI, aF, aG, aO;
                            unpack2(aIF[i][u], aI, aF);
                            unpack2(aGO[i][u], aG, aO);
                            float iv = sigmoidf_(aI + fmaf(wih[j],       x, bsum[j]));
                            float fv = sigmoidf_(aF + fmaf(wih[64 + j],  x, bsum[64 + j]));
                            float gv = tanhf_(   aG + fmaf(wih[128 + j], x, bsum[128 + j]));
                            float ov = sigmoidf_(aO + fmaf(wih[192 + j], x, bsum[192 + j]));
                            float cv = fmaf(fv, cst[i * 16 + u], iv * gv);
                            cst[i * 16 + u] = cv;
                            hv[e] = ov * tanhf_(cv);
                        }
                        *reinterpret_cast<float4*>(sm + wroff + r * HPITCH + u0 + uq * 4)
                            = make_float4(hv[0], hv[1], hv[2], hv[3]);
                    }
                }
                grp_bar(barid);
            } else {
                // t == 7: fuse projection partials; no h store, no barrier
                const float* pWs = sm + OFF_PW;
                const int zb = lay * 128;
                #pragma unroll
                for (int i = 0; i < 2; ++i) {
                    int r = r0 + 32 * i;
                    float x = sm[OFF_X + r * 19 + lay * 8 + 7];
                    float p0 = 0.f, p1 = 0.f;
                    #pragma unroll
                    for (int u = 0; u < 16; ++u) {
                        int j = u0 + u;
                        float aI, aF, aG, aO;
                        unpack2(aIF[i][u], aI, aF);
                        unpack2(aGO[i][u], aG, aO);
                        float iv = sigmoidf_(aI + fmaf(wih[j],       x, bsum[j]));
                        float fv = sigmoidf_(aF + fmaf(wih[64 + j],  x, bsum[64 + j]));
                        float gv = tanhf_(   aG + fmaf(wih[128 + j], x, bsum[128 + j]));
                        float ov = sigmoidf_(aO + fmaf(wih[192 + j], x, bsum[192 + j]));
                        float cv = fmaf(fv, cst[i * 16 + u], iv * gv);
                        float hv = ov * tanhf_(cv);
                        p0 = fmaf(hv, pWs[zb + j],       fmaf(cv, pWs[zb + 64 + j],       p0));
                        p1 = fmaf(hv, pWs[288 + zb + j], fmaf(cv, pWs[288 + zb + 64 + j], p1));
                    }
                    atomicAdd(&sm[OFF_PACC + r * 2 + 0], p0);
                    atomicAdd(&sm[OFF_PACC + r * 2 + 1], p1);
                }
            }
        }

        // ---- stage layer-2 weights (after layer 0 only) ----
        if (lay == 0) {
            __syncthreads();             // both groups done reading layer-1 weights
            for (int i = tid; i < 16384; i += NTHREADS) {
                int k = i & 63, rowi = i >> 6;
                int g = rowi >> 6, j = rowi & 63;
                sm[OFF_W + ((k << 6) + j) * 4 + g] = Whh2[i];
            }
            __syncthreads();
        }
    }
    __syncthreads();   // LSTMs done; h buffers + PACC partials settled

    // ---------------- MLP on feat (2 threads per row, scratch in dead h buffers) ----------------
    {
        const int mr = tid >> 1, mq = tid & 1;
        const float* xr = sm + OFF_X + mr * 19;
        float f0 = xr[16], f1 = xr[17];
        float* h1 = sm + OFF_MH1 + mr * HPITCH;
        float* h2 = sm + OFF_MH2 + mr * HPITCH;

        #pragma unroll
        for (int u = 0; u < 32; ++u) {
            int j = mq * 32 + u;
            float v = fmaf(sm[OFF_MW0 + j * 2], f0,
                      fmaf(sm[OFF_MW0 + j * 2 + 1], f1, sm[OFF_MB0 + j]));
            h1[j] = fmaxf(v, 0.f);
        }
        __syncwarp();

        #pragma unroll
        for (int u = 0; u < 32; ++u) {
            int j = mq * 32 + u;
            float acc = sm[OFF_MB1 + j];
            const float* wr = sm + OFF_MW1 + j * 64;
            #pragma unroll 8
            for (int k = 0; k < 64; ++k) acc = fmaf(h1[k], wr[k], acc);
            h2[j] = fmaxf(acc, 0.f);
        }
        __syncwarp();

        const float* pWs = sm + OFF_PW;
        float pa0 = 0.f, pa1 = 0.f;
        #pragma unroll
        for (int u2 = 0; u2 < 16; ++u2) {
            int j2 = mq * 16 + u2;
            float acc = sm[OFF_MB2 + j2];
            const float* wr = sm + OFF_MW2 + j2 * 64;
            #pragma unroll 8
            for (int k = 0; k < 64; ++k) acc = fmaf(h2[k], wr[k], acc);
            pa0 = fmaf(acc, pWs[256 + j2], pa0);
            pa1 = fmaf(acc, pWs[544 + j2], pa1);
        }
        atomicAdd(&sm[OFF_PACC + mr * 2 + 0], pa0);
        atomicAdd(&sm[OFF_PACC + mr * 2 + 1], pa1);
    }
    __syncthreads();

    {
        int rl = tid >> 1, mm = tid & 1;
        size_t row = (size_t)blockIdx.x * RPB + (size_t)rl;
        out[row * 2 + mm] = sm[OFF_PACC + rl * 2 + mm] + sm[OFF_PB + mm];
    }
}

extern "C" void kernel_launch(void* const* d_in, const int* in_sizes, int n_in,
                              void* d_out, int out_size)
{
    const float* gin  = (const float*)d_in[0];
    const float* Wih1 = (const float*)d_in[1];
    const float* Whh1 = (const float*)d_in[2];
    const float* bih1 = (const float*)d_in[3];
    const float* bhh1 = (const float*)d_in[4];
    const float* Wih2 = (const float*)d_in[5];
    const float* Whh2 = (const float*)d_in[6];
    const float* bih2 = (const float*)d_in[7];
    const float* bhh2 = (const float*)d_in[8];
    const float* mW0  = (const float*)d_in[9];
    const float* mb0  = (const float*)d_in[10];
    const float* mW1  = (const float*)d_in[11];
    const float* mb1  = (const float*)d_in[12];
    const float* mW2  = (const float*)d_in[13];
    const float* mb2  = (const float*)d_in[14];
    const float* pW   = (const float*)d_in[15];
    const float* pb   = (const float*)d_in[16];

    int rows = in_sizes[0] / 18;
    int grid = rows / RPB;

    cudaFuncSetAttribute(lstm_fused_kernel,
                         cudaFuncAttributeMaxDynamicSharedMemorySize, SMEM_BYTES);

    lstm_fused_kernel<<<grid, NTHREADS, SMEM_BYTES>>>(
        gin, Wih1, Whh1, bih1, bhh1, Wih2, Whh2, bih2, bhh2,
        mW0, mb0, mW1, mb1, mW2, mb2, pW, pb, (float*)d_out);
}

// round 14
// speedup vs baseline: 2.2053x; 1.6580x over previous
#include <cuda_runtime.h>
#include <cuda_fp16.h>
#include <cstdint>

#define NTHREADS 256
#define RPB      128

// ---- SMEM ----
// B-fragment region (bytes [0, 163840)):
//   frag(lay, hl, kt, nt) at (((lay*2+hl)*5 + kt)*32 + nt)*256 + lane*8
#define SB_B_BYTES 163840
// float offsets (from float* base)
#define OFF_X    40960                 // 128 x 19
#define OFF_PW   (OFF_X + RPB*19)
#define OFF_MW0  (OFF_PW + 576)
#define OFF_MB0  (OFF_MW0 + 128)
#define OFF_MW1  (OFF_MB0 + 64)
#define OFF_MB1  (OFF_MW1 + 4096)
#define OFF_MW2  (OFF_MB1 + 64)
#define OFF_MB2  (OFF_MW2 + 2048)
#define OFF_PB   (OFF_MB2 + 32)
#define OFF_PACC (OFF_PB + 2)          // [128][2]
#define SMEM_FLOATS (OFF_PACC + RPB*2)
#define SMEM_BYTES  (SMEM_FLOATS * 4)  // ~202.6 KB < 227 KB

// MLP scratch reuses dead B region
#define HPITCH   68
#define OFF_MH1  0
#define OFF_MH2  (RPB*HPITCH)

#define LO_SCALE   2048.0f
#define INV_LO     4.8828125e-4f       // 1/2048, exact

__device__ __forceinline__ unsigned pack_h2u(__half lo, __half hi) {
    unsigned u;
    asm("mov.b32 %0, {%1, %2};" : "=r"(u)
        : "h"(__half_as_ushort(lo)), "h"(__half_as_ushort(hi)));
    return u;
}

__device__ __forceinline__ void mma16816(float* c, const unsigned* a, unsigned b0, unsigned b1) {
    asm volatile(
        "mma.sync.aligned.m16n8k16.row.col.f32.f16.f16.f32 "
        "{%0,%1,%2,%3}, {%4,%5,%6,%7}, {%8,%9}, {%0,%1,%2,%3};"
        : "+f"(c[0]), "+f"(c[1]), "+f"(c[2]), "+f"(c[3])
        : "r"(a[0]), "r"(a[1]), "r"(a[2]), "r"(a[3]), "r"(b0), "r"(b1));
}

__device__ __forceinline__ float sigmoidf_(float x) {
    return __fdividef(1.0f, 1.0f + __expf(-x));
}
__device__ __forceinline__ float tanhf_(float x) {
    float e = __expf(-2.0f * x);
    return __fdividef(1.0f - e, 1.0f + e);
}

__global__ void __launch_bounds__(NTHREADS, 1)
lstm_mma_kernel(const float* __restrict__ gin,
                const float* __restrict__ Wih1, const float* __restrict__ Whh1,
                const float* __restrict__ bih1, const float* __restrict__ bhh1,
                const float* __restrict__ Wih2, const float* __restrict__ Whh2,
                const float* __restrict__ bih2, const float* __restrict__ bhh2,
                const float* __restrict__ mW0,  const float* __restrict__ mb0,
                const float* __restrict__ mW1,  const float* __restrict__ mb1,
                const float* __restrict__ mW2,  const float* __restrict__ mb2,
                const float* __restrict__ pW,   const float* __restrict__ pb,
                float* __restrict__ out)
{
    extern __shared__ char smc[];
    float* smf = reinterpret_cast<float*>(smc);
    const int tid = threadIdx.x;

    // ---------------- staging ----------------
    {
        const float* src = gin + (size_t)blockIdx.x * RPB * 18;
        for (int i = tid; i < RPB * 18; i += NTHREADS)
            smf[OFF_X + (i / 18) * 19 + (i % 18)] = src[i];

        // B fragments: hi, and lo scaled by 2048 (keeps corrections in fp16 normal range)
        for (int idx = tid; idx < 10240; idx += NTHREADS) {
            int ln  = idx & 31;
            int nt  = (idx >> 5) & 31;
            int kt  = (idx >> 10) % 5;
            int lay = idx / 5120;
            int qq  = ln & 3;
            int nn  = (nt << 3) + (ln >> 2);       // global column n = gate*64 + j
            const float* Whh = lay ? Whh2 : Whh1;
            const float* Wih = lay ? Wih2 : Wih1;
            const float* bi_ = lay ? bih2 : bih1;
            const float* bh_ = lay ? bhh2 : bhh1;
            __half vh[4], vl[4];
            #pragma unroll
            for (int d = 0; d < 4; ++d) {
                int k = (kt << 4) + 2 * qq + (d & 1) + ((d >> 1) << 3);
                float v;
                if (kt < 4)       v = Whh[nn * 64 + k];
                else if (k == 64) v = Wih[nn];
                else if (k == 65) v = bi_[nn] + bh_[nn];
                else              v = 0.f;
                __half h = __float2half_rn(v);
                vh[d] = h;
                vl[d] = __float2half_rn((v - __half2float(h)) * LO_SCALE);
            }
            unsigned base = (unsigned)(((lay * 10 + kt) * 32 + nt) * 256 + ln * 8);
            *reinterpret_cast<uint2*>(smc + base)
                = make_uint2(pack_h2u(vh[0], vh[1]), pack_h2u(vh[2], vh[3]));
            *reinterpret_cast<uint2*>(smc + base + 40960)
                = make_uint2(pack_h2u(vl[0], vl[1]), pack_h2u(vl[2], vl[3]));
        }
        for (int i = tid; i < 128;  i += NTHREADS) smf[OFF_MW0 + i] = mW0[i];
        for (int i = tid; i < 4096; i += NTHREADS) smf[OFF_MW1 + i] = mW1[i];
        for (int i = tid; i < 2048; i += NTHREADS) smf[OFF_MW2 + i] = mW2[i];
        for (int i = tid; i < 64;   i += NTHREADS) { smf[OFF_MB0 + i] = mb0[i]; smf[OFF_MB1 + i] = mb1[i]; }
        for (int i = tid; i < 576;  i += NTHREADS) smf[OFF_PW + i] = pW[i];
        for (int i = tid; i < RPB * 2; i += NTHREADS) smf[OFF_PACC + i] = 0.f;
        if (tid < 32) smf[OFF_MB2 + tid] = mb2[tid];
        if (tid < 2)  smf[OFF_PB + tid]  = pb[tid];
        __syncthreads();
    }

    // warp owns rows [16w, 16w+16); lane: q = lane&3, hr = lane>>2; rows r0 = 16w+hr, r0+8
    const int wrp  = tid >> 5;
    const int lane = tid & 31;
    const int q    = lane & 3;
    const int hr   = lane >> 2;
    const int r0   = wrp * 16 + hr;
    const __half ONE_H  = __float2half_rn(1.0f);
    const __half ZERO_H = __float2half_rn(0.0f);

    float pc0[2] = {0.f, 0.f}, pc1[2] = {0.f, 0.f};

    #pragma unroll 1
    for (int lay = 0; lay < 2; ++lay) {
        unsigned aHI[5][4], aLO[5][4];
        #pragma unroll
        for (int kt = 0; kt < 5; ++kt)
            #pragma unroll
            for (int r = 0; r < 4; ++r) { aHI[kt][r] = 0u; aLO[kt][r] = 0u; }
        float cst[2][16];
        #pragma unroll
        for (int rs = 0; rs < 2; ++rs)
            #pragma unroll
            for (int u = 0; u < 16; ++u) cst[rs][u] = 0.f;

        const char* bbase = smc + lay * 81920 + lane * 8;

        #pragma unroll 1
        for (int t = 0; t < 8; ++t) {
            // ktile 4: x and bias slots (lanes q==0 hold k=64,65)
            if (q == 0) {
                float x0 = smf[OFF_X + r0 * 19 + lay * 8 + t];
                float x1 = smf[OFF_X + (r0 + 8) * 19 + lay * 8 + t];
                __half xh0 = __float2half_rn(x0), xh1 = __float2half_rn(x1);
                aHI[4][0] = pack_h2u(xh0, ONE_H);
                aHI[4][1] = pack_h2u(xh1, ONE_H);
                aLO[4][0] = pack_h2u(__float2half_rn((x0 - __half2float(xh0)) * LO_SCALE), ZERO_H);
                aLO[4][1] = pack_h2u(__float2half_rn((x1 - __half2float(xh1)) * LO_SCALE), ZERO_H);
            }

            unsigned nHI[4][4], nLO[4][4];     // staged h[t] fragments; committed after full step

            #pragma unroll
            for (int half = 0; half < 2; ++half) {
                #pragma unroll
                for (int mm = 0; mm < 4; ++mm) {
                    const int m = 4 * half + mm;
                    float G4[4][4];
                    #pragma unroll
                    for (int g = 0; g < 4; ++g) {
                        float cm[4] = {0.f, 0.f, 0.f, 0.f};
                        float cr[4] = {0.f, 0.f, 0.f, 0.f};
                        const char* fb = bbase + (8 * g + m) * 256;
                        #pragma unroll
                        for (int kt = 0; kt < 5; ++kt) {
                            uint2 bh = *reinterpret_cast<const uint2*>(fb + kt * 8192);
                            uint2 bl = *reinterpret_cast<const uint2*>(fb + kt * 8192 + 40960);
                            mma16816(cm, aHI[kt], bh.x, bh.y);   // hi*hi
                            mma16816(cr, aHI[kt], bl.x, bl.y);   // hi*lo (scaled)
                            mma16816(cr, aLO[kt], bh.x, bh.y);   // lo*hi (scaled)
                        }
                        #pragma unroll
                        for (int ci = 0; ci < 4; ++ci)
                            G4[g][ci] = fmaf(cr[ci], INV_LO, cm[ci]);
                    }

                    // epilogue for units j = 8m + 2q + e, rows r0 + 8*rs
                    #pragma unroll
                    for (int rs = 0; rs < 2; ++rs) {
                        float hv[2];
                        #pragma unroll
                        for (int e = 0; e < 2; ++e) {
                            const int ci = rs * 2 + e;
                            float iv = sigmoidf_(G4[0][ci]);
                            float fv = sigmoidf_(G4[1][ci]);
                            float gv = tanhf_(G4[2][ci]);
                            float ov = sigmoidf_(G4[3][ci]);
                            float cv = fmaf(fv, cst[rs][m * 2 + e], iv * gv);
                            cst[rs][m * 2 + e] = cv;
                            float h = ov * tanhf_(cv);
                            hv[e] = h;
                            if (t == 7) {
                                const int j  = 8 * m + 2 * q + e;
                                const int zb = lay * 128;
                                pc0[rs] += fmaf(h, smf[OFF_PW + zb + j],       cv * smf[OFF_PW + zb + 64 + j]);
                                pc1[rs] += fmaf(h, smf[OFF_PW + 288 + zb + j], cv * smf[OFF_PW + 288 + zb + 64 + j]);
                            }
                        }
                        if (t < 7) {
                            const int kt = m >> 1, pr = m & 1;
                            __half h0 = __float2half_rn(hv[0]);
                            __half h1 = __float2half_rn(hv[1]);
                            nHI[kt][rs + 2 * pr] = pack_h2u(h0, h1);
                            nLO[kt][rs + 2 * pr] =
                                pack_h2u(__float2half_rn((hv[0] - __half2float(h0)) * LO_SCALE),
                                         __float2half_rn((hv[1] - __half2float(h1)) * LO_SCALE));
                        }
                    }
                }
            }

            // commit h[t] fragments (Jacobi: no mixing of old/new within a step)
            if (t < 7) {
                #pragma unroll
                for (int kt = 0; kt < 4; ++kt)
                    #pragma unroll
                    for (int r = 0; r < 4; ++r) { aHI[kt][r] = nHI[kt][r]; aLO[kt][r] = nLO[kt][r]; }
            }
        }
    }

    atomicAdd(&smf[OFF_PACC + r0 * 2 + 0],       pc0[0]);
    atomicAdd(&smf[OFF_PACC + r0 * 2 + 1],       pc1[0]);
    atomicAdd(&smf[OFF_PACC + (r0 + 8) * 2 + 0], pc0[1]);
    atomicAdd(&smf[OFF_PACC + (r0 + 8) * 2 + 1], pc1[1]);
    __syncthreads();   // B region dead; PACC partials landed

    // ---------------- MLP on feat (2 threads per row, scratch in dead B region) ----------------
    {
        const int mr = tid >> 1, mq = tid & 1;
        const float* xr = smf + OFF_X + mr * 19;
        float f0 = xr[16], f1 = xr[17];
        float* h1 = smf + OFF_MH1 + mr * HPITCH;
        float* h2 = smf + OFF_MH2 + mr * HPITCH;

        #pragma unroll
        for (int u = 0; u < 32; ++u) {
            int j = mq * 32 + u;
            float v = fmaf(smf[OFF_MW0 + j * 2], f0,
                      fmaf(smf[OFF_MW0 + j * 2 + 1], f1, smf[OFF_MB0 + j]));
            h1[j] = fmaxf(v, 0.f);
        }
        __syncwarp();

        #pragma unroll
        for (int u = 0; u < 32; ++u) {
            int j = mq * 32 + u;
            float acc = smf[OFF_MB1 + j];
            const float* wr = smf + OFF_MW1 + j * 64;
            #pragma unroll 8
            for (int k = 0; k < 64; ++k) acc = fmaf(h1[k], wr[k], acc);
            h2[j] = fmaxf(acc, 0.f);
        }
        __syncwarp();

        const float* pWs = smf + OFF_PW;
        float pa0 = 0.f, pa1 = 0.f;
        #pragma unroll
        for (int u2 = 0; u2 < 16; ++u2) {
            int j2 = mq * 16 + u2;
            float acc = smf[OFF_MB2 + j2];
            const float* wr = smf + OFF_MW2 + j2 * 64;
            #pragma unroll 8
            for (int k = 0; k < 64; ++k) acc = fmaf(h2[k], wr[k], acc);
            pa0 = fmaf(acc, pWs[256 + j2], pa0);
            pa1 = fmaf(acc, pWs[544 + j2], pa1);
        }
        atomicAdd(&smf[OFF_PACC + mr * 2 + 0], pa0);
        atomicAdd(&smf[OFF_PACC + mr * 2 + 1], pa1);
    }
    __syncthreads();

    {
        int rl = tid >> 1, mm = tid & 1;
        size_t row = (size_t)blockIdx.x * RPB + (size_t)rl;
        out[row * 2 + mm] = smf[OFF_PACC + rl * 2 + mm] + smf[OFF_PB + mm];
    }
}

extern "C" void kernel_launch(void* const* d_in, const int* in_sizes, int n_in,
                              void* d_out, int out_size)
{
    const float* gin  = (const float*)d_in[0];
    const float* Wih1 = (const float*)d_in[1];
    const float* Whh1 = (const float*)d_in[2];
    const float* bih1 = (const float*)d_in[3];
    const float* bhh1 = (const float*)d_in[4];
    const float* Wih2 = (const float*)d_in[5];
    const float* Whh2 = (const float*)d_in[6];
    const float* bih2 = (const float*)d_in[7];
    const float* bhh2 = (const float*)d_in[8];
    const float* mW0  = (const float*)d_in[9];
    const float* mb0  = (const float*)d_in[10];
    const float* mW1  = (const float*)d_in[11];
    const float* mb1  = (const float*)d_in[12];
    const float* mW2  = (const float*)d_in[13];
    const float* mb2  = (const float*)d_in[14];
    const float* pW   = (const float*)d_in[15];
    const float* pb   = (const float*)d_in[16];

    int rows = in_sizes[0] / 18;
    int grid = rows / RPB;

    cudaFuncSetAttribute(lstm_mma_kernel,
                         cudaFuncAttributeMaxDynamicSharedMemorySize, SMEM_BYTES);

    lstm_mma_kernel<<<grid, NTHREADS, SMEM_BYTES>>>(
        gin, Wih1, Whh1, bih1, bhh1, Wih2, Whh2, bih2, bhh2,
        mW0, mb0, mW1, mb1, mW2, mb2, pW, pb, (float*)d_out);
}

// round 15
// speedup vs baseline: 2.4609x; 1.1159x over previous
#include <cuda_runtime.h>
#include <cuda_fp16.h>
#include <cstdint>

#define NTHREADS 384
#define RPB      192

// ---- SMEM ----
// B-fragment region (bytes [0, 163840)):
//   frag(lay, hl, kt, nt) at (((lay*2+hl)*5 + kt)*32 + nt)*256 + lane*8
#define SB_B_BYTES 163840
// float offsets (from float* base)
#define OFF_X    40960                 // 192 x 19
#define OFF_PW   (OFF_X + RPB*19)
#define OFF_MW0  (OFF_PW + 576)
#define OFF_MB0  (OFF_MW0 + 128)
#define OFF_MW1  (OFF_MB0 + 64)
#define OFF_MB1  (OFF_MW1 + 4096)
#define OFF_MW2  (OFF_MB1 + 64)
#define OFF_MB2  (OFF_MW2 + 2048)
#define OFF_PB   (OFF_MB2 + 32)
#define OFF_PACC (OFF_PB + 2)          // [192][2]
#define SMEM_FLOATS (OFF_PACC + RPB*2)
#define SMEM_BYTES  (SMEM_FLOATS * 4)  // ~208 KB < 227 KB

// MLP scratch reuses dead B region
#define HPITCH   68
#define OFF_MH1  0
#define OFF_MH2  (RPB*HPITCH)

#define LO_SCALE   2048.0f
#define INV_LO     4.8828125e-4f       // 1/2048, exact

__device__ __forceinline__ unsigned pack_h2u(__half lo, __half hi) {
    unsigned u;
    asm("mov.b32 %0, {%1, %2};" : "=r"(u)
        : "h"(__half_as_ushort(lo)), "h"(__half_as_ushort(hi)));
    return u;
}

__device__ __forceinline__ void mma16816(float* c, const unsigned* a, unsigned b0, unsigned b1) {
    asm volatile(
        "mma.sync.aligned.m16n8k16.row.col.f32.f16.f16.f32 "
        "{%0,%1,%2,%3}, {%4,%5,%6,%7}, {%8,%9}, {%0,%1,%2,%3};"
        : "+f"(c[0]), "+f"(c[1]), "+f"(c[2]), "+f"(c[3])
        : "r"(a[0]), "r"(a[1]), "r"(a[2]), "r"(a[3]), "r"(b0), "r"(b1));
}

__device__ __forceinline__ float sigmoidf_(float x) {
    return __fdividef(1.0f, 1.0f + __expf(-x));
}
__device__ __forceinline__ float tanhf_(float x) {
    float e = __expf(-2.0f * x);
    return __fdividef(1.0f - e, 1.0f + e);
}

__global__ void __launch_bounds__(NTHREADS, 1)
lstm_mma_kernel(const float* __restrict__ gin,
                const float* __restrict__ Wih1, const float* __restrict__ Whh1,
                const float* __restrict__ bih1, const float* __restrict__ bhh1,
                const float* __restrict__ Wih2, const float* __restrict__ Whh2,
                const float* __restrict__ bih2, const float* __restrict__ bhh2,
                const float* __restrict__ mW0,  const float* __restrict__ mb0,
                const float* __restrict__ mW1,  const float* __restrict__ mb1,
                const float* __restrict__ mW2,  const float* __restrict__ mb2,
                const float* __restrict__ pW,   const float* __restrict__ pb,
                float* __restrict__ out, int nrows)
{
    extern __shared__ char smc[];
    float* smf = reinterpret_cast<float*>(smc);
    const int tid = threadIdx.x;
    const int rowbase = blockIdx.x * RPB;

    // ---------------- staging ----------------
    {
        for (int i = tid; i < RPB * 18; i += NTHREADS) {
            int rl = i / 18;
            int grow = rowbase + rl;
            smf[OFF_X + rl * 19 + (i % 18)] =
                (grow < nrows) ? gin[(size_t)grow * 18 + (i % 18)] : 0.f;
        }

        // B fragments: hi, and lo scaled by 2048 (keeps corrections in fp16 normal range)
        for (int idx = tid; idx < 10240; idx += NTHREADS) {
            int ln  = idx & 31;
            int nt  = (idx >> 5) & 31;
            int kt  = (idx >> 10) % 5;
            int lay = idx / 5120;
            int qq  = ln & 3;
            int nn  = (nt << 3) + (ln >> 2);       // global column n = gate*64 + j
            const float* Whh = lay ? Whh2 : Whh1;
            const float* Wih = lay ? Wih2 : Wih1;
            const float* bi_ = lay ? bih2 : bih1;
            const float* bh_ = lay ? bhh2 : bhh1;
            __half vh[4], vl[4];
            #pragma unroll
            for (int d = 0; d < 4; ++d) {
                int k = (kt << 4) + 2 * qq + (d & 1) + ((d >> 1) << 3);
                float v;
                if (kt < 4)       v = Whh[nn * 64 + k];
                else if (k == 64) v = Wih[nn];
                else if (k == 65) v = bi_[nn] + bh_[nn];
                else              v = 0.f;
                __half h = __float2half_rn(v);
                vh[d] = h;
                vl[d] = __float2half_rn((v - __half2float(h)) * LO_SCALE);
            }
            unsigned base = (unsigned)(((lay * 10 + kt) * 32 + nt) * 256 + ln * 8);
            *reinterpret_cast<uint2*>(smc + base)
                = make_uint2(pack_h2u(vh[0], vh[1]), pack_h2u(vh[2], vh[3]));
            *reinterpret_cast<uint2*>(smc + base + 40960)
                = make_uint2(pack_h2u(vl[0], vl[1]), pack_h2u(vl[2], vl[3]));
        }
        for (int i = tid; i < 128;  i += NTHREADS) smf[OFF_MW0 + i] = mW0[i];
        for (int i = tid; i < 4096; i += NTHREADS) smf[OFF_MW1 + i] = mW1[i];
        for (int i = tid; i < 2048; i += NTHREADS) smf[OFF_MW2 + i] = mW2[i];
        for (int i = tid; i < 64;   i += NTHREADS) { smf[OFF_MB0 + i] = mb0[i]; smf[OFF_MB1 + i] = mb1[i]; }
        for (int i = tid; i < 576;  i += NTHREADS) smf[OFF_PW + i] = pW[i];
        for (int i = tid; i < RPB * 2; i += NTHREADS) smf[OFF_PACC + i] = 0.f;
        if (tid < 32) smf[OFF_MB2 + tid] = mb2[tid];
        if (tid < 2)  smf[OFF_PB + tid]  = pb[tid];
        __syncthreads();
    }

    // warp owns rows [16w, 16w+16); lane: q = lane&3, hr = lane>>2; rows r0 = 16w+hr, r0+8
    const int wrp  = tid >> 5;
    const int lane = tid & 31;
    const int q    = lane & 3;
    const int hr   = lane >> 2;
    const int r0   = wrp * 16 + hr;
    const __half ONE_H  = __float2half_rn(1.0f);
    const __half ZERO_H = __float2half_rn(0.0f);

    float pc0[2] = {0.f, 0.f}, pc1[2] = {0.f, 0.f};

    #pragma unroll 1
    for (int lay = 0; lay < 2; ++lay) {
        unsigned aHI[5][4], aLO[5][4];
        #pragma unroll
        for (int kt = 0; kt < 5; ++kt)
            #pragma unroll
            for (int r = 0; r < 4; ++r) { aHI[kt][r] = 0u; aLO[kt][r] = 0u; }
        float cst[2][16];
        #pragma unroll
        for (int rs = 0; rs < 2; ++rs)
            #pragma unroll
            for (int u = 0; u < 16; ++u) cst[rs][u] = 0.f;

        const char* bbase = smc + lay * 81920 + lane * 8;

        #pragma unroll 1
        for (int t = 0; t < 8; ++t) {
            // ktile 4: x and bias slots (lanes q==0 hold k=64,65)
            if (q == 0) {
                float x0 = smf[OFF_X + r0 * 19 + lay * 8 + t];
                float x1 = smf[OFF_X + (r0 + 8) * 19 + lay * 8 + t];
                __half xh0 = __float2half_rn(x0), xh1 = __float2half_rn(x1);
                aHI[4][0] = pack_h2u(xh0, ONE_H);
                aHI[4][1] = pack_h2u(xh1, ONE_H);
                aLO[4][0] = pack_h2u(__float2half_rn((x0 - __half2float(xh0)) * LO_SCALE), ZERO_H);
                aLO[4][1] = pack_h2u(__float2half_rn((x1 - __half2float(xh1)) * LO_SCALE), ZERO_H);
            }

            unsigned nHI[4][4], nLO[4][4];     // staged h[t] fragments; committed after full step

            #pragma unroll
            for (int half = 0; half < 2; ++half) {
                #pragma unroll
                for (int mm = 0; mm < 4; ++mm) {
                    const int m = 4 * half + mm;
                    float G4[4][4];
                    #pragma unroll
                    for (int g = 0; g < 4; ++g) {
                        float cm[4] = {0.f, 0.f, 0.f, 0.f};
                        float cr[4] = {0.f, 0.f, 0.f, 0.f};
                        const char* fb = bbase + (8 * g + m) * 256;
                        #pragma unroll
                        for (int kt = 0; kt < 5; ++kt) {
                            uint2 bh = *reinterpret_cast<const uint2*>(fb + kt * 8192);
                            uint2 bl = *reinterpret_cast<const uint2*>(fb + kt * 8192 + 40960);
                            mma16816(cm, aHI[kt], bh.x, bh.y);   // hi*hi
                            mma16816(cr, aHI[kt], bl.x, bl.y);   // hi*lo (scaled)
                            mma16816(cr, aLO[kt], bh.x, bh.y);   // lo*hi (scaled)
                        }
                        #pragma unroll
                        for (int ci = 0; ci < 4; ++ci)
                            G4[g][ci] = fmaf(cr[ci], INV_LO, cm[ci]);
                    }

                    // epilogue for units j = 8m + 2q + e, rows r0 + 8*rs
                    #pragma unroll
                    for (int rs = 0; rs < 2; ++rs) {
                        float hv[2];
                        #pragma unroll
                        for (int e = 0; e < 2; ++e) {
                            const int ci = rs * 2 + e;
                            float iv = sigmoidf_(G4[0][ci]);
                            float fv = sigmoidf_(G4[1][ci]);
                            float gv = tanhf_(G4[2][ci]);
                            float ov = sigmoidf_(G4[3][ci]);
                            float cv = fmaf(fv, cst[rs][m * 2 + e], iv * gv);
                            cst[rs][m * 2 + e] = cv;
                            float h = ov * tanhf_(cv);
                            hv[e] = h;
                            if (t == 7) {
                                const int j  = 8 * m + 2 * q + e;
                                const int zb = lay * 128;
                                pc0[rs] += fmaf(h, smf[OFF_PW + zb + j],       cv * smf[OFF_PW + zb + 64 + j]);
                                pc1[rs] += fmaf(h, smf[OFF_PW + 288 + zb + j], cv * smf[OFF_PW + 288 + zb + 64 + j]);
                            }
                        }
                        if (t < 7) {
                            const int kt = m >> 1, pr = m & 1;
                            __half h0 = __float2half_rn(hv[0]);
                            __half h1 = __float2half_rn(hv[1]);
                            nHI[kt][rs + 2 * pr] = pack_h2u(h0, h1);
                            nLO[kt][rs + 2 * pr] =
                                pack_h2u(__float2half_rn((hv[0] - __half2float(h0)) * LO_SCALE),
                                         __float2half_rn((hv[1] - __half2float(h1)) * LO_SCALE));
                        }
                    }
                }
            }

            // commit h[t] fragments (Jacobi: no mixing of old/new within a step)
            if (t < 7) {
                #pragma unroll
                for (int kt = 0; kt < 4; ++kt)
                    #pragma unroll
                    for (int r = 0; r < 4; ++r) { aHI[kt][r] = nHI[kt][r]; aLO[kt][r] = nLO[kt][r]; }
            }
        }
    }

    atomicAdd(&smf[OFF_PACC + r0 * 2 + 0],       pc0[0]);
    atomicAdd(&smf[OFF_PACC + r0 * 2 + 1],       pc1[0]);
    atomicAdd(&smf[OFF_PACC + (r0 + 8) * 2 + 0], pc0[1]);
    atomicAdd(&smf[OFF_PACC + (r0 + 8) * 2 + 1], pc1[1]);
    __syncthreads();   // B region dead; PACC partials landed

    // ---------------- MLP on feat (2 threads per row, scratch in dead B region) ----------------
    {
        const int mr = tid >> 1, mq = tid & 1;
        const float* xr = smf + OFF_X + mr * 19;
        float f0 = xr[16], f1 = xr[17];
        float* h1 = smf + OFF_MH1 + mr * HPITCH;
        float* h2 = smf + OFF_MH2 + mr * HPITCH;

        #pragma unroll
        for (int u = 0; u < 32; ++u) {
            int j = mq * 32 + u;
            float v = fmaf(smf[OFF_MW0 + j * 2], f0,
                      fmaf(smf[OFF_MW0 + j * 2 + 1], f1, smf[OFF_MB0 + j]));
            h1[j] = fmaxf(v, 0.f);
        }
        __syncwarp();

        #pragma unroll
        for (int u = 0; u < 32; ++u) {
            int j = mq * 32 + u;
            float acc = smf[OFF_MB1 + j];
            const float* wr = smf + OFF_MW1 + j * 64;
            #pragma unroll 8
            for (int k = 0; k < 64; ++k) acc = fmaf(h1[k], wr[k], acc);
            h2[j] = fmaxf(acc, 0.f);
        }
        __syncwarp();

        const float* pWs = smf + OFF_PW;
        float pa0 = 0.f, pa1 = 0.f;
        #pragma unroll
        for (int u2 = 0; u2 < 16; ++u2) {
            int j2 = mq * 16 + u2;
            float acc = smf[OFF_MB2 + j2];
            const float* wr = smf + OFF_MW2 + j2 * 64;
            #pragma unroll 8
            for (int k = 0; k < 64; ++k) acc = fmaf(h2[k], wr[k], acc);
            pa0 = fmaf(acc, pWs[256 + j2], pa0);
            pa1 = fmaf(acc, pWs[544 + j2], pa1);
        }
        atomicAdd(&smf[OFF_PACC + mr * 2 + 0], pa0);
        atomicAdd(&smf[OFF_PACC + mr * 2 + 1], pa1);
    }
    __syncthreads();

    {
        int rl = tid >> 1, mm = tid & 1;
        int grow = rowbase + rl;
        if (grow < nrows)
            out[(size_t)grow * 2 + mm] = smf[OFF_PACC + rl * 2 + mm] + smf[OFF_PB + mm];
    }
}

extern "C" void kernel_launch(void* const* d_in, const int* in_sizes, int n_in,
                              void* d_out, int out_size)
{
    const float* gin  = (const float*)d_in[0];
    const float* Wih1 = (const float*)d_in[1];
    const float* Whh1 = (const float*)d_in[2];
    const float* bih1 = (const float*)d_in[3];
    const float* bhh1 = (const float*)d_in[4];
    const float* Wih2 = (const float*)d_in[5];
    const float* Whh2 = (const float*)d_in[6];
    const float* bih2 = (const float*)d_in[7];
    const float* bhh2 = (const float*)d_in[8];
    const float* mW0  = (const float*)d_in[9];
    const float* mb0  = (const float*)d_in[10];
    const float* mW1  = (const float*)d_in[11];
    const float* mb1  = (const float*)d_in[12];
    const float* mW2  = (const float*)d_in[13];
    const float* mb2  = (const float*)d_in[14];
    const float* pW   = (const float*)d_in[15];
    const float* pb   = (const float*)d_in[16];

    int nrows = in_sizes[0] / 18;
    int grid = (nrows + RPB - 1) / RPB;

    cudaFuncSetAttribute(lstm_mma_kernel,
                         cudaFuncAttributeMaxDynamicSharedMemorySize, SMEM_BYTES);

    lstm_mma_kernel<<<grid, NTHREADS, SMEM_BYTES>>>(
        gin, Wih1, Whh1, bih1, bhh1, Wih2, Whh2, bih2, bhh2,
        mW0, mb0, mW1, mb1, mW2, mb2, pW, pb, (float*)d_out, nrows);
}

// round 16
// speedup vs baseline: 2.9443x; 1.1964x over previous
#include <cuda_runtime.h>
#include <cuda_fp16.h>
#include <cstdint>

#define NTHREADS 384
#define RPB      192

// ---- SMEM ----
// B-fragment region (bytes [0, 163840)):
//   frag(lay, hl, kt, nt) at (((lay*2+hl)*5 + kt)*32 + nt)*256 + lane*8
#define SB_B_BYTES 163840
// float offsets (from float* base)
#define OFF_X    40960                 // 192 x 19
#define OFF_PW   (OFF_X + RPB*19)
#define OFF_MW0  (OFF_PW + 576)
#define OFF_MB0  (OFF_MW0 + 128)
#define OFF_MW1  (OFF_MB0 + 64)
#define OFF_MB1  (OFF_MW1 + 4096)
#define OFF_MW2  (OFF_MB1 + 64)
#define OFF_MB2  (OFF_MW2 + 2048)
#define OFF_PB   (OFF_MB2 + 32)
#define OFF_PACC (OFF_PB + 2)          // [192][2]
#define SMEM_FLOATS (OFF_PACC + RPB*2)
#define SMEM_BYTES  (SMEM_FLOATS * 4)  // ~208 KB < 227 KB

// MLP scratch reuses dead B region
#define HPITCH   68
#define OFF_MH1  0
#define OFF_MH2  (RPB*HPITCH)

#define LO_SCALE   2048.0f
#define INV_LO     4.8828125e-4f       // 1/2048, exact

__device__ __forceinline__ unsigned pack_h2u(__half lo, __half hi) {
    unsigned u;
    asm("mov.b32 %0, {%1, %2};" : "=r"(u)
        : "h"(__half_as_ushort(lo)), "h"(__half_as_ushort(hi)));
    return u;
}

__device__ __forceinline__ void mma16816(float* c, const unsigned* a, unsigned b0, unsigned b1) {
    asm volatile(
        "mma.sync.aligned.m16n8k16.row.col.f32.f16.f16.f32 "
        "{%0,%1,%2,%3}, {%4,%5,%6,%7}, {%8,%9}, {%0,%1,%2,%3};"
        : "+f"(c[0]), "+f"(c[1]), "+f"(c[2]), "+f"(c[3])
        : "r"(a[0]), "r"(a[1]), "r"(a[2]), "r"(a[3]), "r"(b0), "r"(b1));
}

// MUFU.TANH (sm_75+): 1 instruction, ~2^-11 max error
__device__ __forceinline__ float tanh_ap(float x) {
    float y;
    asm("tanh.approx.f32 %0, %1;" : "=f"(y) : "f"(x));
    return y;
}
__device__ __forceinline__ float sigmoid_ap(float x) {
    return fmaf(0.5f, tanh_ap(0.5f * x), 0.5f);
}

__global__ void __launch_bounds__(NTHREADS, 1)
lstm_mma_kernel(const float* __restrict__ gin,
                const float* __restrict__ Wih1, const float* __restrict__ Whh1,
                const float* __restrict__ bih1, const float* __restrict__ bhh1,
                const float* __restrict__ Wih2, const float* __restrict__ Whh2,
                const float* __restrict__ bih2, const float* __restrict__ bhh2,
                const float* __restrict__ mW0,  const float* __restrict__ mb0,
                const float* __restrict__ mW1,  const float* __restrict__ mb1,
                const float* __restrict__ mW2,  const float* __restrict__ mb2,
                const float* __restrict__ pW,   const float* __restrict__ pb,
                float* __restrict__ out, int nrows)
{
    extern __shared__ char smc[];
    float* smf = reinterpret_cast<float*>(smc);
    const int tid = threadIdx.x;
    const int rowbase = blockIdx.x * RPB;

    // ---------------- staging ----------------
    {
        for (int i = tid; i < RPB * 18; i += NTHREADS) {
            int rl = i / 18;
            int grow = rowbase + rl;
            smf[OFF_X + rl * 19 + (i % 18)] =
                (grow < nrows) ? gin[(size_t)grow * 18 + (i % 18)] : 0.f;
        }

        // B fragments: hi, and lo scaled by 2048 (keeps corrections in fp16 normal range)
        for (int idx = tid; idx < 10240; idx += NTHREADS) {
            int ln  = idx & 31;
            int nt  = (idx >> 5) & 31;
            int kt  = (idx >> 10) % 5;
            int lay = idx / 5120;
            int qq  = ln & 3;
            int nn  = (nt << 3) + (ln >> 2);       // global column n = gate*64 + j
            const float* Whh = lay ? Whh2 : Whh1;
            const float* Wih = lay ? Wih2 : Wih1;
            const float* bi_ = lay ? bih2 : bih1;
            const float* bh_ = lay ? bhh2 : bhh1;
            __half vh[4], vl[4];
            #pragma unroll
            for (int d = 0; d < 4; ++d) {
                int k = (kt << 4) + 2 * qq + (d & 1) + ((d >> 1) << 3);
                float v;
                if (kt < 4)       v = Whh[nn * 64 + k];
                else if (k == 64) v = Wih[nn];
                else if (k == 65) v = bi_[nn] + bh_[nn];
                else              v = 0.f;
                __half h = __float2half_rn(v);
                vh[d] = h;
                vl[d] = __float2half_rn((v - __half2float(h)) * LO_SCALE);
            }
            unsigned base = (unsigned)(((lay * 10 + kt) * 32 + nt) * 256 + ln * 8);
            *reinterpret_cast<uint2*>(smc + base)
                = make_uint2(pack_h2u(vh[0], vh[1]), pack_h2u(vh[2], vh[3]));
            *reinterpret_cast<uint2*>(smc + base + 40960)
                = make_uint2(pack_h2u(vl[0], vl[1]), pack_h2u(vl[2], vl[3]));
        }
        for (int i = tid; i < 128;  i += NTHREADS) smf[OFF_MW0 + i] = mW0[i];
        for (int i = tid; i < 4096; i += NTHREADS) smf[OFF_MW1 + i] = mW1[i];
        for (int i = tid; i < 2048; i += NTHREADS) smf[OFF_MW2 + i] = mW2[i];
        for (int i = tid; i < 64;   i += NTHREADS) { smf[OFF_MB0 + i] = mb0[i]; smf[OFF_MB1 + i] = mb1[i]; }
        for (int i = tid; i < 576;  i += NTHREADS) smf[OFF_PW + i] = pW[i];
        for (int i = tid; i < RPB * 2; i += NTHREADS) smf[OFF_PACC + i] = 0.f;
        if (tid < 32) smf[OFF_MB2 + tid] = mb2[tid];
        if (tid < 2)  smf[OFF_PB + tid]  = pb[tid];
        __syncthreads();
    }

    // warp owns rows [16w, 16w+16); lane: q = lane&3, hr = lane>>2; rows r0 = 16w+hr, r0+8
    const int wrp  = tid >> 5;
    const int lane = tid & 31;
    const int q    = lane & 3;
    const int hr   = lane >> 2;
    const int r0   = wrp * 16 + hr;
    const __half ONE_H  = __float2half_rn(1.0f);
    const __half ZERO_H = __float2half_rn(0.0f);

    float pc0[2] = {0.f, 0.f}, pc1[2] = {0.f, 0.f};

    #pragma unroll 1
    for (int lay = 0; lay < 2; ++lay) {
        unsigned aHI[5][4], aLO[5][4];
        #pragma unroll
        for (int kt = 0; kt < 5; ++kt)
            #pragma unroll
            for (int r = 0; r < 4; ++r) { aHI[kt][r] = 0u; aLO[kt][r] = 0u; }
        float cst[2][16];
        #pragma unroll
        for (int rs = 0; rs < 2; ++rs)
            #pragma unroll
            for (int u = 0; u < 16; ++u) cst[rs][u] = 0.f;

        const char* bbase = smc + lay * 81920 + lane * 8;

        #pragma unroll 1
        for (int t = 0; t < 8; ++t) {
            // ktile 4: x and bias slots (lanes q==0 hold k=64,65)
            if (q == 0) {
                float x0 = smf[OFF_X + r0 * 19 + lay * 8 + t];
                float x1 = smf[OFF_X + (r0 + 8) * 19 + lay * 8 + t];
                __half xh0 = __float2half_rn(x0), xh1 = __float2half_rn(x1);
                aHI[4][0] = pack_h2u(xh0, ONE_H);
                aHI[4][1] = pack_h2u(xh1, ONE_H);
                aLO[4][0] = pack_h2u(__float2half_rn((x0 - __half2float(xh0)) * LO_SCALE), ZERO_H);
                aLO[4][1] = pack_h2u(__float2half_rn((x1 - __half2float(xh1)) * LO_SCALE), ZERO_H);
            }

            unsigned nHI[4][4], nLO[4][4];     // staged h[t] fragments; committed after full step

            #pragma unroll
            for (int half = 0; half < 2; ++half) {
                #pragma unroll
                for (int mm = 0; mm < 4; ++mm) {
                    const int m = 4 * half + mm;
                    float G4[4][4];
                    #pragma unroll
                    for (int g = 0; g < 4; ++g) {
                        float cm[4] = {0.f, 0.f, 0.f, 0.f};
                        float cr[4] = {0.f, 0.f, 0.f, 0.f};
                        const char* fb = bbase + (8 * g + m) * 256;
                        #pragma unroll
                        for (int kt = 0; kt < 5; ++kt) {
                            uint2 bh = *reinterpret_cast<const uint2*>(fb + kt * 8192);
                            uint2 bl = *reinterpret_cast<const uint2*>(fb + kt * 8192 + 40960);
                            mma16816(cm, aHI[kt], bh.x, bh.y);   // hi*hi
                            mma16816(cr, aHI[kt], bl.x, bl.y);   // hi*lo (scaled)
                            mma16816(cr, aLO[kt], bh.x, bh.y);   // lo*hi (scaled)
                        }
                        #pragma unroll
                        for (int ci = 0; ci < 4; ++ci)
                            G4[g][ci] = fmaf(cr[ci], INV_LO, cm[ci]);
                    }

                    // epilogue for units j = 8m + 2q + e, rows r0 + 8*rs
                    #pragma unroll
                    for (int rs = 0; rs < 2; ++rs) {
                        float hv[2];
                        #pragma unroll
                        for (int e = 0; e < 2; ++e) {
                            const int ci = rs * 2 + e;
                            float iv = sigmoid_ap(G4[0][ci]);
                            float fv = sigmoid_ap(G4[1][ci]);
                            float gv = tanh_ap(G4[2][ci]);
                            float ov = sigmoid_ap(G4[3][ci]);
                            float cv = fmaf(fv, cst[rs][m * 2 + e], iv * gv);
                            cst[rs][m * 2 + e] = cv;
                            float h = ov * tanh_ap(cv);
                            hv[e] = h;
                            if (t == 7) {
                                const int j  = 8 * m + 2 * q + e;
                                const int zb = lay * 128;
                                pc0[rs] += fmaf(h, smf[OFF_PW + zb + j],       cv * smf[OFF_PW + zb + 64 + j]);
                                pc1[rs] += fmaf(h, smf[OFF_PW + 288 + zb + j], cv * smf[OFF_PW + 288 + zb + 64 + j]);
                            }
                        }
                        if (t < 7) {
                            const int kt = m >> 1, pr = m & 1;
                            __half h0 = __float2half_rn(hv[0]);
                            __half h1 = __float2half_rn(hv[1]);
                            nHI[kt][rs + 2 * pr] = pack_h2u(h0, h1);
                            nLO[kt][rs + 2 * pr] =
                                pack_h2u(__float2half_rn((hv[0] - __half2float(h0)) * LO_SCALE),
                                         __float2half_rn((hv[1] - __half2float(h1)) * LO_SCALE));
                        }
                    }
                }
            }

            // commit h[t] fragments (Jacobi: no mixing of old/new within a step)
            if (t < 7) {
                #pragma unroll
                for (int kt = 0; kt < 4; ++kt)
                    #pragma unroll
                    for (int r = 0; r < 4; ++r) { aHI[kt][r] = nHI[kt][r]; aLO[kt][r] = nLO[kt][r]; }
            }
        }
    }

    atomicAdd(&smf[OFF_PACC + r0 * 2 + 0],       pc0[0]);
    atomicAdd(&smf[OFF_PACC + r0 * 2 + 1],       pc1[0]);
    atomicAdd(&smf[OFF_PACC + (r0 + 8) * 2 + 0], pc0[1]);
    atomicAdd(&smf[OFF_PACC + (r0 + 8) * 2 + 1], pc1[1]);
    __syncthreads();   // B region dead; PACC partials landed

    // ---------------- MLP on feat (2 threads per row, scratch in dead B region) ----------------
    {
        const int mr = tid >> 1, mq = tid & 1;
        const float* xr = smf + OFF_X + mr * 19;
        float f0 = xr[16], f1 = xr[17];
        float* h1 = smf + OFF_MH1 + mr * HPITCH;
        float* h2 = smf + OFF_MH2 + mr * HPITCH;

        #pragma unroll
        for (int u = 0; u < 32; ++u) {
            int j = mq * 32 + u;
            float v = fmaf(smf[OFF_MW0 + j * 2], f0,
                      fmaf(smf[OFF_MW0 + j * 2 + 1], f1, smf[OFF_MB0 + j]));
            h1[j] = fmaxf(v, 0.f);
        }
        __syncwarp();

        #pragma unroll
        for (int u = 0; u < 32; ++u) {
            int j = mq * 32 + u;
            float acc = smf[OFF_MB1 + j];
            const float* wr = smf + OFF_MW1 + j * 64;
            #pragma unroll 8
            for (int k = 0; k < 64; ++k) acc = fmaf(h1[k], wr[k], acc);
            h2[j] = fmaxf(acc, 0.f);
        }
        __syncwarp();

        const float* pWs = smf + OFF_PW;
        float pa0 = 0.f, pa1 = 0.f;
        #pragma unroll
        for (int u2 = 0; u2 < 16; ++u2) {
            int j2 = mq * 16 + u2;
            float acc = smf[OFF_MB2 + j2];
            const float* wr = smf + OFF_MW2 + j2 * 64;
            #pragma unroll 8
            for (int k = 0; k < 64; ++k) acc = fmaf(h2[k], wr[k], acc);
            pa0 = fmaf(acc, pWs[256 + j2], pa0);
            pa1 = fmaf(acc, pWs[544 + j2], pa1);
        }
        atomicAdd(&smf[OFF_PACC + mr * 2 + 0], pa0);
        atomicAdd(&smf[OFF_PACC + mr * 2 + 1], pa1);
    }
    __syncthreads();

    {
        int rl = tid >> 1, mm = tid & 1;
        int grow = rowbase + rl;
        if (grow < nrows)
            out[(size_t)grow * 2 + mm] = smf[OFF_PACC + rl * 2 + mm] + smf[OFF_PB + mm];
    }
}

extern "C" void kernel_launch(void* const* d_in, const int* in_sizes, int n_in,
                              void* d_out, int out_size)
{
    const float* gin  = (const float*)d_in[0];
    const float* Wih1 = (const float*)d_in[1];
    const float* Whh1 = (const float*)d_in[2];
    const float* bih1 = (const float*)d_in[3];
    const float* bhh1 = (const float*)d_in[4];
    const float* Wih2 = (const float*)d_in[5];
    const float* Whh2 = (const float*)d_in[6];
    const float* bih2 = (const float*)d_in[7];
    const float* bhh2 = (const float*)d_in[8];
    const float* mW0  = (const float*)d_in[9];
    const float* mb0  = (const float*)d_in[10];
    const float* mW1  = (const float*)d_in[11];
    const float* mb1  = (const float*)d_in[12];
    const float* mW2  = (const float*)d_in[13];
    const float* mb2  = (const float*)d_in[14];
    const float* pW   = (const float*)d_in[15];
    const float* pb   = (const float*)d_in[16];

    int nrows = in_sizes[0] / 18;
    int grid = (nrows + RPB - 1) / RPB;

    cudaFuncSetAttribute(lstm_mma_kernel,
                         cudaFuncAttributeMaxDynamicSharedMemorySize, SMEM_BYTES);

    lstm_mma_kernel<<<grid, NTHREADS, SMEM_BYTES>>>(
        gin, Wih1, Whh1, bih1, bhh1, Wih2, Whh2, bih2, bhh2,
        mW0, mb0, mW1, mb1, mW2, mb2, pW, pb, (float*)d_out, nrows);
}

// round 17
// speedup vs baseline: 3.6366x; 1.2351x over previous
#include <cuda_runtime.h>
#include <cuda_fp16.h>
#include <cstdint>

#define NTHREADS 384
#define RPB      192

// ---- SMEM ----
// B-fragment region (bytes [0, 163840)):
//   hi frag(lay, kt, nt) at ((lay*10 + kt)*32 + nt)*256 + lane*8 ; lo at +40960
#define SB_B_BYTES 163840
// float offsets (from float* base)
#define OFF_X    40960                 // 192 x 19
#define OFF_PW   (OFF_X + RPB*19)
#define OFF_MW0  (OFF_PW + 576)
#define OFF_MB0  (OFF_MW0 + 128)
#define OFF_MW1  (OFF_MB0 + 64)
#define OFF_MB1  (OFF_MW1 + 4096)
#define OFF_MW2  (OFF_MB1 + 64)
#define OFF_MB2  (OFF_MW2 + 2048)
#define OFF_PB   (OFF_MB2 + 32)
#define OFF_PACC (OFF_PB + 2)          // [192][2]
#define SMEM_FLOATS (OFF_PACC + RPB*2)
#define SMEM_BYTES  (SMEM_FLOATS * 4)  // ~208 KB < 227 KB

// MLP scratch reuses dead B region
#define HPITCH   68
#define OFF_MH1  0
#define OFF_MH2  (RPB*HPITCH)

#define LO_SCALE   2048.0f
#define INV_LO     4.8828125e-4f       // 1/2048, exact

__device__ __forceinline__ unsigned pack_h2u(__half lo, __half hi) {
    unsigned u;
    asm("mov.b32 %0, {%1, %2};" : "=r"(u)
        : "h"(__half_as_ushort(lo)), "h"(__half_as_ushort(hi)));
    return u;
}

__device__ __forceinline__ void mma16816(float* c, const unsigned* a, unsigned b0, unsigned b1) {
    asm volatile(
        "mma.sync.aligned.m16n8k16.row.col.f32.f16.f16.f32 "
        "{%0,%1,%2,%3}, {%4,%5,%6,%7}, {%8,%9}, {%0,%1,%2,%3};"
        : "+f"(c[0]), "+f"(c[1]), "+f"(c[2]), "+f"(c[3])
        : "r"(a[0]), "r"(a[1]), "r"(a[2]), "r"(a[3]), "r"(b0), "r"(b1));
}

// MUFU.TANH (sm_75+): 1 instruction, ~2^-11 max error
__device__ __forceinline__ float tanh_ap(float x) {
    float y;
    asm("tanh.approx.f32 %0, %1;" : "=f"(y) : "f"(x));
    return y;
}
__device__ __forceinline__ float sigmoid_ap(float x) {
    return fmaf(0.5f, tanh_ap(0.5f * x), 0.5f);
}

__global__ void __launch_bounds__(NTHREADS, 1)
lstm_mma_kernel(const float* __restrict__ gin,
                const float* __restrict__ Wih1, const float* __restrict__ Whh1,
                const float* __restrict__ bih1, const float* __restrict__ bhh1,
                const float* __restrict__ Wih2, const float* __restrict__ Whh2,
                const float* __restrict__ bih2, const float* __restrict__ bhh2,
                const float* __restrict__ mW0,  const float* __restrict__ mb0,
                const float* __restrict__ mW1,  const float* __restrict__ mb1,
                const float* __restrict__ mW2,  const float* __restrict__ mb2,
                const float* __restrict__ pW,   const float* __restrict__ pb,
                float* __restrict__ out, int nrows)
{
    extern __shared__ char smc[];
    float* smf = reinterpret_cast<float*>(smc);
    const int tid = threadIdx.x;
    const int rowbase = blockIdx.x * RPB;

    // ---------------- staging ----------------
    {
        for (int i = tid; i < RPB * 18; i += NTHREADS) {
            int rl = i / 18;
            int grow = rowbase + rl;
            smf[OFF_X + rl * 19 + (i % 18)] =
                (grow < nrows) ? gin[(size_t)grow * 18 + (i % 18)] : 0.f;
        }

        // B fragments: hi, and lo scaled by 2048 (keeps corrections in fp16 normal range)
        for (int idx = tid; idx < 10240; idx += NTHREADS) {
            int ln  = idx & 31;
            int nt  = (idx >> 5) & 31;
            int kt  = (idx >> 10) % 5;
            int lay = idx / 5120;
            int qq  = ln & 3;
            int nn  = (nt << 3) + (ln >> 2);       // global column n = gate*64 + j
            const float* Whh = lay ? Whh2 : Whh1;
            const float* Wih = lay ? Wih2 : Wih1;
            const float* bi_ = lay ? bih2 : bih1;
            const float* bh_ = lay ? bhh2 : bhh1;
            __half vh[4], vl[4];
            #pragma unroll
            for (int d = 0; d < 4; ++d) {
                int k = (kt << 4) + 2 * qq + (d & 1) + ((d >> 1) << 3);
                float v;
                if (kt < 4)       v = Whh[nn * 64 + k];
                else if (k == 64) v = Wih[nn];
                else if (k == 65) v = bi_[nn] + bh_[nn];
                else              v = 0.f;
                __half h = __float2half_rn(v);
                vh[d] = h;
                vl[d] = __float2half_rn((v - __half2float(h)) * LO_SCALE);
            }
            unsigned base = (unsigned)(((lay * 10 + kt) * 32 + nt) * 256 + ln * 8);
            *reinterpret_cast<uint2*>(smc + base)
                = make_uint2(pack_h2u(vh[0], vh[1]), pack_h2u(vh[2], vh[3]));
            *reinterpret_cast<uint2*>(smc + base + 40960)
                = make_uint2(pack_h2u(vl[0], vl[1]), pack_h2u(vl[2], vl[3]));
        }
        for (int i = tid; i < 128;  i += NTHREADS) smf[OFF_MW0 + i] = mW0[i];
        for (int i = tid; i < 4096; i += NTHREADS) smf[OFF_MW1 + i] = mW1[i];
        for (int i = tid; i < 2048; i += NTHREADS) smf[OFF_MW2 + i] = mW2[i];
        for (int i = tid; i < 64;   i += NTHREADS) { smf[OFF_MB0 + i] = mb0[i]; smf[OFF_MB1 + i] = mb1[i]; }
        for (int i = tid; i < 576;  i += NTHREADS) smf[OFF_PW + i] = pW[i];
        for (int i = tid; i < RPB * 2; i += NTHREADS) smf[OFF_PACC + i] = 0.f;
        if (tid < 32) smf[OFF_MB2 + tid] = mb2[tid];
        if (tid < 2)  smf[OFF_PB + tid]  = pb[tid];
        __syncthreads();
    }

    // warp owns rows [16w, 16w+16); lane: q = lane&3, hr = lane>>2; rows r0 = 16w+hr, r0+8
    const int wrp  = tid >> 5;
    const int lane = tid & 31;
    const int q    = lane & 3;
    const int hr   = lane >> 2;
    const int r0   = wrp * 16 + hr;
    const __half ONE_H  = __float2half_rn(1.0f);

    float pc0[2] = {0.f, 0.f}, pc1[2] = {0.f, 0.f};

    #pragma unroll 1
    for (int lay = 0; lay < 2; ++lay) {
        unsigned aHI[5][4];
        #pragma unroll
        for (int kt = 0; kt < 5; ++kt)
            #pragma unroll
            for (int r = 0; r < 4; ++r) aHI[kt][r] = 0u;
        float cst[2][16];
        #pragma unroll
        for (int rs = 0; rs < 2; ++rs)
            #pragma unroll
            for (int u = 0; u < 16; ++u) cst[rs][u] = 0.f;

        const char* bbase = smc + lay * 81920 + lane * 8;

        #pragma unroll 1
        for (int t = 0; t < 8; ++t) {
            // ktile 4: x and bias slots (lanes q==0 hold k=64,65)
            if (q == 0) {
                float x0 = smf[OFF_X + r0 * 19 + lay * 8 + t];
                float x1 = smf[OFF_X + (r0 + 8) * 19 + lay * 8 + t];
                aHI[4][0] = pack_h2u(__float2half_rn(x0), ONE_H);
                aHI[4][1] = pack_h2u(__float2half_rn(x1), ONE_H);
            }

            unsigned nHI[4][4];     // staged h[t] fragments; committed after full step

            #pragma unroll
            for (int half = 0; half < 2; ++half) {
                #pragma unroll
                for (int mm = 0; mm < 4; ++mm) {
                    const int m = 4 * half + mm;
                    float G4[4][4];
                    #pragma unroll
                    for (int g = 0; g < 4; ++g) {
                        float cm[4] = {0.f, 0.f, 0.f, 0.f};
                        float cr[4] = {0.f, 0.f, 0.f, 0.f};
                        const char* fb = bbase + (8 * g + m) * 256;
                        #pragma unroll
                        for (int kt = 0; kt < 5; ++kt) {
                            uint2 bh = *reinterpret_cast<const uint2*>(fb + kt * 8192);
                            uint2 bl = *reinterpret_cast<const uint2*>(fb + kt * 8192 + 40960);
                            mma16816(cm, aHI[kt], bh.x, bh.y);   // hi*hi
                            mma16816(cr, aHI[kt], bl.x, bl.y);   // hi*lo (scaled; systematic W correction)
                        }
                        #pragma unroll
                        for (int ci = 0; ci < 4; ++ci)
                            G4[g][ci] = fmaf(cr[ci], INV_LO, cm[ci]);
                    }

                    // epilogue for units j = 8m + 2q + e, rows r0 + 8*rs
                    #pragma unroll
                    for (int rs = 0; rs < 2; ++rs) {
                        float hv[2];
                        #pragma unroll
                        for (int e = 0; e < 2; ++e) {
                            const int ci = rs * 2 + e;
                            float iv = sigmoid_ap(G4[0][ci]);
                            float fv = sigmoid_ap(G4[1][ci]);
                            float gv = tanh_ap(G4[2][ci]);
                            float ov = sigmoid_ap(G4[3][ci]);
                            float cv = fmaf(fv, cst[rs][m * 2 + e], iv * gv);
                            cst[rs][m * 2 + e] = cv;
                            float h = ov * tanh_ap(cv);
                            hv[e] = h;
                            if (t == 7) {
                                const int j  = 8 * m + 2 * q + e;
                                const int zb = lay * 128;
                                pc0[rs] += fmaf(h, smf[OFF_PW + zb + j],       cv * smf[OFF_PW + zb + 64 + j]);
                                pc1[rs] += fmaf(h, smf[OFF_PW + 288 + zb + j], cv * smf[OFF_PW + 288 + zb + 64 + j]);
                            }
                        }
                        if (t < 7) {
                            const int kt = m >> 1, pr = m & 1;
                            nHI[kt][rs + 2 * pr] =
                                pack_h2u(__float2half_rn(hv[0]), __float2half_rn(hv[1]));
                        }
                    }
                }
            }

            // commit h[t] fragments (Jacobi: no mixing of old/new within a step)
            if (t < 7) {
                #pragma unroll
                for (int kt = 0; kt < 4; ++kt)
                    #pragma unroll
                    for (int r = 0; r < 4; ++r) aHI[kt][r] = nHI[kt][r];
            }
        }
    }

    atomicAdd(&smf[OFF_PACC + r0 * 2 + 0],       pc0[0]);
    atomicAdd(&smf[OFF_PACC + r0 * 2 + 1],       pc1[0]);
    atomicAdd(&smf[OFF_PACC + (r0 + 8) * 2 + 0], pc0[1]);
    atomicAdd(&smf[OFF_PACC + (r0 + 8) * 2 + 1], pc1[1]);
    __syncthreads();   // B region dead; PACC partials landed

    // ---------------- MLP on feat (2 threads per row, scratch in dead B region) ----------------
    {
        const int mr = tid >> 1, mq = tid & 1;
        const float* xr = smf + OFF_X + mr * 19;
        float f0 = xr[16], f1 = xr[17];
        float* h1 = smf + OFF_MH1 + mr * HPITCH;
        float* h2 = smf + OFF_MH2 + mr * HPITCH;

        #pragma unroll
        for (int u = 0; u < 32; ++u) {
            int j = mq * 32 + u;
            float v = fmaf(smf[OFF_MW0 + j * 2], f0,
                      fmaf(smf[OFF_MW0 + j * 2 + 1], f1, smf[OFF_MB0 + j]));
            h1[j] = fmaxf(v, 0.f);
        }
        __syncwarp();

        #pragma unroll
        for (int u = 0; u < 32; ++u) {
            int j = mq * 32 + u;
            float acc = smf[OFF_MB1 + j];
            const float* wr = smf + OFF_MW1 + j * 64;
            #pragma unroll 8
            for (int k = 0; k < 64; ++k) acc = fmaf(h1[k], wr[k], acc);
            h2[j] = fmaxf(acc, 0.f);
        }
        __syncwarp();

        const float* pWs = smf + OFF_PW;
        float pa0 = 0.f, pa1 = 0.f;
        #pragma unroll
        for (int u2 = 0; u2 < 16; ++u2) {
            int j2 = mq * 16 + u2;
            float acc = smf[OFF_MB2 + j2];
            const float* wr = smf + OFF_MW2 + j2 * 64;
            #pragma unroll 8
            for (int k = 0; k < 64; ++k) acc = fmaf(h2[k], wr[k], acc);
            pa0 = fmaf(acc, pWs[256 + j2], pa0);
            pa1 = fmaf(acc, pWs[544 + j2], pa1);
        }
        atomicAdd(&smf[OFF_PACC + mr * 2 + 0], pa0);
        atomicAdd(&smf[OFF_PACC + mr * 2 + 1], pa1);
    }
    __syncthreads();

    {
        int rl = tid >> 1, mm = tid & 1;
        int grow = rowbase + rl;
        if (grow < nrows)
            out[(size_t)grow * 2 + mm] = smf[OFF_PACC + rl * 2 + mm] + smf[OFF_PB + mm];
    }
}

extern "C" void kernel_launch(void* const* d_in, const int* in_sizes, int n_in,
                              void* d_out, int out_size)
{
    const float* gin  = (const float*)d_in[0];
    const float* Wih1 = (const float*)d_in[1];
    const float* Whh1 = (const float*)d_in[2];
    const float* bih1 = (const float*)d_in[3];
    const float* bhh1 = (const float*)d_in[4];
    const float* Wih2 = (const float*)d_in[5];
    const float* Whh2 = (const float*)d_in[6];
    const float* bih2 = (const float*)d_in[7];
    const float* bhh2 = (const float*)d_in[8];
    const float* mW0  = (const float*)d_in[9];
    const float* mb0  = (const float*)d_in[10];
    const float* mW1  = (const float*)d_in[11];
    const float* mb1  = (const float*)d_in[12];
    const float* mW2  = (const float*)d_in[13];
    const float* mb2  = (const float*)d_in[14];
    const float* pW   = (const float*)d_in[15];
    const float* pb   = (const float*)d_in[16];

    int nrows = in_sizes[0] / 18;
    int grid = (nrows + RPB - 1) / RPB;

    cudaFuncSetAttribute(lstm_mma_kernel,
                         cudaFuncAttributeMaxDynamicSharedMemorySize, SMEM_BYTES);

    lstm_mma_kernel<<<grid, NTHREADS, SMEM_BYTES>>>(
        gin, Wih1, Whh1, bih1, bhh1, Wih2, Whh2, bih2, bhh2,
        mW0, mb0, mW1, mb1, mW2, mb2, pW, pb, (float*)d_out, nrows);
}